// round 14
// baseline (speedup 1.0000x reference)
#include <cuda_runtime.h>
#include <cuda_bf16.h>
#include <cstdint>
#include <math.h>

#define EE   4
#define LL   2
#define BB   4
#define NN   1024
#define SS   1025
#define DIN  2048
#define DD   512
#define HH   8
#define DHD  64
#define MLPD 512
#define NC   4
#define BS   (BB*SS)        // 4100

// ---------------- scratch (device globals) ----------------
__device__ float g_h   [(size_t)EE*BS*DD];
__device__ float g_qkv [(size_t)EE*BS*3*DD];
__device__ float g_rbuf[(size_t)BB*NN*DD];
__device__ float g_r   [BB*DD];
__device__ float g_gs  [BB*EE];
__device__ float g_lat [EE*BB*DD];
__device__ float g_mixl[BB*DD];
// bf16 triplet activations (A side: hi,hi,lo -> width 3K)
__device__ __nv_bfloat16 g_x3  [(size_t)BB*NN*3*DIN];
__device__ __nv_bfloat16 g_hn3 [(size_t)EE*BS*3*DD];
__device__ __nv_bfloat16 g_ao3 [(size_t)EE*BS*3*DD];
__device__ __nv_bfloat16 g_mlp3[(size_t)EE*BS*3*MLPD];
// bf16 triplet weights (B side: [N,3K], hi,lo,hi)
__device__ __nv_bfloat16 g_Wr3  [(size_t)DD*3*DIN];
__device__ __nv_bfloat16 g_Wp3  [(size_t)EE*DD*3*DIN];
__device__ __nv_bfloat16 g_Wqkv3[(size_t)EE*LL*(3*DD)*(3*DD)];
__device__ __nv_bfloat16 g_Wo3  [(size_t)EE*LL*DD*(3*DD)];
__device__ __nv_bfloat16 g_Wm13 [(size_t)EE*LL*MLPD*(3*DD)];
__device__ __nv_bfloat16 g_Wm23 [(size_t)EE*LL*DD*(3*MLPD)];

// ---------------- helpers ----------------
__device__ __forceinline__ uint32_t smem_u32(const void* p) {
    uint32_t a;
    asm("{ .reg .u64 t; cvta.to.shared.u64 t, %1; cvt.u32.u64 %0, t; }" : "=r"(a) : "l"(p));
    return a;
}
#define SW128(off) ((off) ^ (((off) >> 3) & 0x70))

__device__ __forceinline__ void ldm_x4(uint32_t* r, uint32_t addr) {
    asm volatile("ldmatrix.sync.aligned.m8n8.x4.shared.b16 {%0,%1,%2,%3}, [%4];"
        : "=r"(r[0]), "=r"(r[1]), "=r"(r[2]), "=r"(r[3]) : "r"(addr));
}
__device__ __forceinline__ void mma16816(float* d, const uint32_t* a, const uint32_t* b) {
    asm volatile("mma.sync.aligned.m16n8k16.row.col.f32.bf16.bf16.f32 "
        "{%0,%1,%2,%3}, {%4,%5,%6,%7}, {%8,%9}, {%0,%1,%2,%3};"
        : "+f"(d[0]), "+f"(d[1]), "+f"(d[2]), "+f"(d[3])
        : "r"(a[0]), "r"(a[1]), "r"(a[2]), "r"(a[3]), "r"(b[0]), "r"(b[1]));
}
__device__ __forceinline__ void cp16(uint32_t dst, const void* src, int bytes) {
    asm volatile("cp.async.cg.shared.global [%0], [%1], 16, %2;"
        :: "r"(dst), "l"(src), "r"(bytes));
}
#define CP_COMMIT() asm volatile("cp.async.commit_group;" ::: "memory")
#define CP_WAIT1()  asm volatile("cp.async.wait_group 1;" ::: "memory")
#define CP_WAIT0()  asm volatile("cp.async.wait_group 0;" ::: "memory")

__device__ __forceinline__ float gelu_tanh(float x) {
    float x3 = x * x * x;
    float t  = tanhf(0.7978845608028654f * (x + 0.044715f * x3));
    return 0.5f * x * (1.0f + t);
}
__device__ __forceinline__ void split2(float v, __nv_bfloat16& hi, __nv_bfloat16& lo) {
    hi = __float2bfloat16(v);
    lo = __float2bfloat16(v - __bfloat162float(hi));
}
__device__ __forceinline__ float blockReduceSum(float v) {
    __shared__ float sh[32];
    int lane = threadIdx.x & 31, wid = threadIdx.x >> 5;
    #pragma unroll
    for (int o = 16; o > 0; o >>= 1) v += __shfl_xor_sync(0xffffffffu, v, o);
    if (lane == 0) sh[wid] = v;
    __syncthreads();
    int nw = (blockDim.x + 31) >> 5;
    if (wid == 0) {
        float t = (lane < nw) ? sh[lane] : 0.f;
        #pragma unroll
        for (int o = 16; o > 0; o >>= 1) t += __shfl_xor_sync(0xffffffffu, t, o);
        if (lane == 0) sh[0] = t;
    }
    __syncthreads();
    float r = sh[0];
    __syncthreads();
    return r;
}

// fragment loader for one ks step (A: 4x m16k16 frags, B: 2x ldm_x4 = n32k16)
__device__ __forceinline__ void load_frags(uint32_t asb, uint32_t bsb, int ks,
                                           int wm, int wn, int lane,
                                           uint32_t afr[4][4], uint32_t bfr[2][4]) {
    #pragma unroll
    for (int mi = 0; mi < 4; mi++) {
        int ar = wm * 64 + mi * 16 + (lane & 15);
        int ac = ks * 32 + (lane >> 4) * 16;
        ldm_x4(afr[mi], asb + SW128((uint32_t)(ar * 128 + ac)));
    }
    #pragma unroll
    for (int np = 0; np < 2; np++) {
        int nr = wn * 32 + np * 16 + (lane & 7) + ((lane >> 4) & 1) * 8;
        int bc = ks * 32 + ((lane >> 3) & 1) * 16;
        ldm_x4(bfr[np], bsb + SW128((uint32_t)(nr * 128 + bc)));
    }
}

// =======================================================================
// mma.sync GEMM, cp.async double-buffered smem + ping-pong register frags.
// D[M,N] = act(A3[M,3K] . B3[N,3K]^T + bias [+Res])
// 128x128 CTA tile (dynamic smem 64KB), 8 warps (2x4), warp tile 64x32.
// =======================================================================
template <int ACT, bool REMAP, bool HASRES, bool OUTTRIP>
__global__ __launch_bounds__(256) void tgemm_k(
    const __nv_bfloat16* __restrict__ A3, const __nv_bfloat16* __restrict__ B3,
    const float* __restrict__ bias, const float* __restrict__ Res,
    float* __restrict__ Cf, __nv_bfloat16* __restrict__ Ct,
    int M, int N, int Kp,
    long long sA, long long sB, long long sBias, long long sRes, long long sC,
    int mapN, int mapS)
{
    extern __shared__ __align__(128) char smem[];
    // layout: A0 @0, A1 @16K, B0 @32K, B1 @48K (each 128 rows x 128B)
    const int tid = threadIdx.x, wid = tid >> 5, lane = tid & 31;
    const long long e = blockIdx.z;
    A3 += e * sA; B3 += e * sB; bias += e * sBias;
    const int brow = blockIdx.y * 128, bcol = blockIdx.x * 128;
    const int wm = wid >> 2, wn = wid & 3;          // 2 x 4 warp grid

    float acc[4][4][4];
    #pragma unroll
    for (int i = 0; i < 4; i++)
        #pragma unroll
        for (int j = 0; j < 4; j++)
            #pragma unroll
            for (int f = 0; f < 4; f++) acc[i][j][f] = 0.f;

    const uint32_t sbase = smem_u32(smem);
    const uint32_t sa[2]  = { sbase, sbase + 16384 };
    const uint32_t sbm[2] = { sbase + 32768, sbase + 49152 };

    // per-thread load geometry: 4 rows (tid>>3 + 32p), column byte (tid&7)*16
    const int baseRow = tid >> 3;
    const int cb = (tid & 7) * 16;
    uint32_t swoff[4];
    int aok[4]; long long arow[4], browi[4];
    #pragma unroll
    for (int p = 0; p < 4; p++) {
        int row = baseRow + 32 * p;
        swoff[p] = SW128((uint32_t)(row * 128 + cb));
        int gr = brow + row;
        aok[p]  = (gr < M) ? 16 : 0;
        arow[p] = (gr < M) ? gr : (M - 1);
        browi[p] = bcol + row;
    }
    const int NCk = Kp >> 6;

    // prologue: chunk 0 -> buf 0
    #pragma unroll
    for (int p = 0; p < 4; p++) {
        cp16(sa[0]  + swoff[p], (const char*)(A3 + arow[p]  * Kp) + cb, aok[p]);
        cp16(sbm[0] + swoff[p], (const char*)(B3 + browi[p] * Kp) + cb, 16);
    }
    CP_COMMIT();

    uint32_t afr[2][4][4], bfr[2][2][4];   // ping-pong fragment sets

    for (int c = 0; c < NCk; c++) {
        const int buf = c & 1;
        if (c + 1 < NCk) {
            const int nb = buf ^ 1;
            #pragma unroll
            for (int p = 0; p < 4; p++) {
                cp16(sa[nb]  + swoff[p],
                     (const char*)(A3 + arow[p]  * Kp + (c + 1) * 64) + cb, aok[p]);
                cp16(sbm[nb] + swoff[p],
                     (const char*)(B3 + browi[p] * Kp + (c + 1) * 64) + cb, 16);
            }
            CP_COMMIT();
            CP_WAIT1();
        } else {
            CP_WAIT0();
        }
        __syncthreads();

        const uint32_t asb = sa[buf], bsb = sbm[buf];
        // software-pipelined ks loop: load ks+1 frags while ks MMAs run
        load_frags(asb, bsb, 0, wm, wn, lane, afr[0], bfr[0]);
        #pragma unroll
        for (int ks = 0; ks < 4; ks++) {
            if (ks < 3)
                load_frags(asb, bsb, ks + 1, wm, wn, lane,
                           afr[(ks + 1) & 1], bfr[(ks + 1) & 1]);
            const int pb = ks & 1;
            #pragma unroll
            for (int mi = 0; mi < 4; mi++)
                #pragma unroll
                for (int ni = 0; ni < 4; ni++)
                    mma16816(acc[mi][ni], afr[pb][mi], &bfr[pb][ni >> 1][(ni & 1) * 2]);
        }
        __syncthreads();
    }

    // ---- epilogue from registers ----
    #pragma unroll
    for (int mi = 0; mi < 4; mi++) {
        #pragma unroll
        for (int half = 0; half < 2; half++) {
            int row = brow + wm * 64 + mi * 16 + (lane >> 2) + half * 8;
            if (row >= M) continue;
            long long orow = row;
            if (REMAP) orow = (long long)(row / mapN) * mapS + 1 + (row % mapN);
            #pragma unroll
            for (int ni = 0; ni < 4; ni++) {
                int col = bcol + wn * 32 + ni * 8 + (lane & 3) * 2;
                float v0 = acc[mi][ni][half * 2 + 0] + bias[col];
                float v1 = acc[mi][ni][half * 2 + 1] + bias[col + 1];
                if (HASRES) {
                    float2 rr = *(const float2*)(Res + e * sRes + orow * (long long)N + col);
                    v0 += rr.x; v1 += rr.y;
                }
                if (ACT == 1) { v0 = fmaxf(v0, 0.f); v1 = fmaxf(v1, 0.f); }
                else if (ACT == 2) { v0 = gelu_tanh(v0); v1 = gelu_tanh(v1); }
                if (OUTTRIP) {
                    __nv_bfloat16* op = Ct + e * sC + orow * (long long)(3 * N) + 3 * col;
                    __nv_bfloat16 h0, l0, h1, l1;
                    split2(v0, h0, l0); split2(v1, h1, l1);
                    op[0] = h0; op[1] = h0; op[2] = l0;
                    op[3] = h1; op[4] = h1; op[5] = l1;
                } else {
                    float* cp = Cf + e * sC + orow * (long long)N + col;
                    *(float2*)cp = make_float2(v0, v1);
                }
            }
        }
    }
}

// ---------------- conversions ----------------
__global__ void aconv_k(const float* __restrict__ X, __nv_bfloat16* __restrict__ X3,
                        int Kdim, long long total)
{
    long long idx = (long long)blockIdx.x * blockDim.x + threadIdx.x;
    if (idx >= total) return;
    long long m = idx / Kdim;
    int k = (int)(idx - m * Kdim);
    __nv_bfloat16 hi, lo; split2(X[idx], hi, lo);
    long long base = m * (long long)(3 * Kdim) + 3 * k;
    X3[base] = hi; X3[base + 1] = hi; X3[base + 2] = lo;
}

// W[K,N] -> W3[N,3K] (hi,lo,hi), batched over z
__global__ void wconv_k(const float* __restrict__ W, __nv_bfloat16* __restrict__ W3,
                        int K, int N)
{
    __shared__ float t[32][33];
    const int n0 = blockIdx.x * 32, k0 = blockIdx.y * 32;
    const float* Wb = W + (long long)blockIdx.z * K * N;
    __nv_bfloat16* Ob = W3 + (long long)blockIdx.z * N * 3 * K;
    const int tx = threadIdx.x, ty = threadIdx.y;
    for (int i = ty; i < 32; i += 8)
        t[i][tx] = Wb[(long long)(k0 + i) * N + n0 + tx];
    __syncthreads();
    for (int i = ty; i < 32; i += 8) {
        int n = n0 + i;
        __nv_bfloat16 hi, lo; split2(t[tx][i], hi, lo);
        long long base = (long long)n * 3 * K + 3 * (k0 + tx);
        Ob[base] = hi; Ob[base + 1] = lo; Ob[base + 2] = hi;
    }
}

// ---------------- LayerNorm -> bf16 triplets ----------------
__global__ __launch_bounds__(128) void ln3_k(
    const float* __restrict__ X, const float* __restrict__ G,
    const float* __restrict__ Bt, __nv_bfloat16* __restrict__ Y3,
    long long xb, long long xr, long long yb, long long yr, long long gs)
{
    const long long e = blockIdx.y;
    const float* x = X + e * xb + (long long)blockIdx.x * xr;
    __nv_bfloat16* y = Y3 + e * yb + (long long)blockIdx.x * yr;
    const float* g = G + e * gs;
    const float* b = Bt + e * gs;
    const int tid = threadIdx.x;

    float4 v = *(const float4*)(x + tid * 4);
    float s = blockReduceSum(v.x + v.y + v.z + v.w);
    float mean = s * (1.f / 512.f);
    float dx = v.x - mean, dy = v.y - mean, dz = v.z - mean, dw = v.w - mean;
    float s2 = blockReduceSum(dx * dx + dy * dy + dz * dz + dw * dw);
    float rstd = rsqrtf(s2 * (1.f / 512.f) + 1e-5f);
    float4 gv = *(const float4*)(g + tid * 4);
    float4 bv = *(const float4*)(b + tid * 4);
    float o[4] = { dx * rstd * gv.x + bv.x, dy * rstd * gv.y + bv.y,
                   dz * rstd * gv.z + bv.z, dw * rstd * gv.w + bv.w };
    #pragma unroll
    for (int j = 0; j < 4; j++) {
        __nv_bfloat16 hi, lo; split2(o[j], hi, lo);
        long long base = 3 * (long long)(tid * 4 + j);
        y[base] = hi; y[base + 1] = hi; y[base + 2] = lo;
    }
}

// ---------------- LayerNorm fp32 out ----------------
__global__ __launch_bounds__(128) void ln_k(
    const float* __restrict__ X, const float* __restrict__ G,
    const float* __restrict__ Bt, float* __restrict__ Y,
    long long xb, long long xr, long long yb, long long yr, long long gs)
{
    const long long e = blockIdx.y;
    const float* x = X + e * xb + (long long)blockIdx.x * xr;
    float*       y = Y + e * yb + (long long)blockIdx.x * yr;
    const float* g = G + e * gs;
    const float* b = Bt + e * gs;
    const int tid = threadIdx.x;

    float4 v = *(const float4*)(x + tid * 4);
    float s = blockReduceSum(v.x + v.y + v.z + v.w);
    float mean = s * (1.f / 512.f);
    float dx = v.x - mean, dy = v.y - mean, dz = v.z - mean, dw = v.w - mean;
    float s2 = blockReduceSum(dx * dx + dy * dy + dz * dz + dw * dw);
    float rstd = rsqrtf(s2 * (1.f / 512.f) + 1e-5f);
    float4 gv = *(const float4*)(g + tid * 4);
    float4 bv = *(const float4*)(b + tid * 4);
    float4 o;
    o.x = dx * rstd * gv.x + bv.x;
    o.y = dy * rstd * gv.y + bv.y;
    o.z = dz * rstd * gv.z + bv.z;
    o.w = dw * rstd * gv.w + bv.w;
    *(float4*)(y + tid * 4) = o;
}

__global__ void cls_init_k(const float* __restrict__ cls) {
    int idx = blockIdx.x * blockDim.x + threadIdx.x;
    if (idx >= EE * BB * DD) return;
    int d = idx & (DD - 1);
    int r = idx >> 9;
    int b = r & (BB - 1);
    int e = r >> 2;
    g_h[((long long)e * BS + (long long)b * SS) * DD + d] = cls[e * DD + d];
}

// ---------------- flash attention (fp32; triplet epilogue) ----------------
#define ATK 80
__global__ __launch_bounds__(128) void attn_k(int S) {
    const int e  = blockIdx.z;
    const int bh = blockIdx.y;
    const int b  = bh >> 3, h = bh & 7;
    const float* qkv = g_qkv + (long long)e * BS * 3 * DD + (long long)b * SS * 3 * DD;
    __nv_bfloat16* o3 = g_ao3 + ((long long)e * BS + (long long)b * SS) * 3 * DD;

    __shared__ float Ks[ATK][DHD];
    __shared__ float Vs[ATK][DHD];

    const int tid = threadIdx.x;
    const int q   = blockIdx.x * 128 + tid;
    const bool qv = (q < S);
    const int qr  = qv ? q : (S - 1);

    float qreg[DHD];
    {
        const float* qp = qkv + (long long)qr * (3 * DD) + h * DHD;
        #pragma unroll
        for (int d = 0; d < DHD; d += 4) {
            float4 t = *(const float4*)(qp + d);
            qreg[d] = t.x; qreg[d + 1] = t.y; qreg[d + 2] = t.z; qreg[d + 3] = t.w;
        }
    }

    float m = -1e30f, l = 0.f;
    float acc[DHD];
    #pragma unroll
    for (int d = 0; d < DHD; d++) acc[d] = 0.f;
    const float scale = 0.125f;

    for (int kt = 0; kt < S; kt += ATK) {
        int nrows = S - kt; if (nrows > ATK) nrows = ATK;
        for (int i = tid * 4; i < ATK * DHD; i += 128 * 4) {
            int r = i >> 6, c = i & 63;
            if (r < nrows) {
                const float* base = qkv + (long long)(kt + r) * (3 * DD) + DD + h * DHD + c;
                *(float4*)(&Ks[r][c]) = *(const float4*)(base);
                *(float4*)(&Vs[r][c]) = *(const float4*)(base + DD);
            } else {
                float4 z = make_float4(0.f, 0.f, 0.f, 0.f);
                *(float4*)(&Ks[r][c]) = z;
                *(float4*)(&Vs[r][c]) = z;
            }
        }
        __syncthreads();

        #pragma unroll 1
        for (int c0 = 0; c0 < ATK; c0 += 16) {
            float sc[16];
            #pragma unroll
            for (int jj = 0; jj < 16; jj++) {
                float s = 0.f;
                const float* kp = &Ks[c0 + jj][0];
                #pragma unroll
                for (int d = 0; d < DHD; d += 4) {
                    float4 kk = *(const float4*)(kp + d);
                    s = fmaf(qreg[d], kk.x, s);
                    s = fmaf(qreg[d + 1], kk.y, s);
                    s = fmaf(qreg[d + 2], kk.z, s);
                    s = fmaf(qreg[d + 3], kk.w, s);
                }
                sc[jj] = (kt + c0 + jj < S) ? s * scale : -1e30f;
            }
            float mloc = sc[0];
            #pragma unroll
            for (int jj = 1; jj < 16; jj++) mloc = fmaxf(mloc, sc[jj]);
            float mnew = fmaxf(m, mloc);
            float corr = __expf(m - mnew);
            l *= corr;
            #pragma unroll
            for (int d = 0; d < DHD; d++) acc[d] *= corr;
            #pragma unroll
            for (int jj = 0; jj < 16; jj++) {
                float p = __expf(sc[jj] - mnew);
                l += p;
                const float* vp = &Vs[c0 + jj][0];
                #pragma unroll
                for (int d = 0; d < DHD; d += 4) {
                    float4 vv = *(const float4*)(vp + d);
                    acc[d]     = fmaf(p, vv.x, acc[d]);
                    acc[d + 1] = fmaf(p, vv.y, acc[d + 1]);
                    acc[d + 2] = fmaf(p, vv.z, acc[d + 2]);
                    acc[d + 3] = fmaf(p, vv.w, acc[d + 3]);
                }
            }
            m = mnew;
        }
        __syncthreads();
    }

    if (qv) {
        float inv = 1.f / l;
        __nv_bfloat16* op = o3 + (long long)q * (3 * DD) + 3 * (h * DHD);
        #pragma unroll
        for (int d = 0; d < DHD; d++) {
            float v = acc[d] * inv;
            __nv_bfloat16 hi, lo; split2(v, hi, lo);
            op[3 * d] = hi; op[3 * d + 1] = hi; op[3 * d + 2] = lo;
        }
    }
}

// ---------------- router / gate / mix / head ----------------
__global__ void router_reduce_k() {
    int idx = blockIdx.x * blockDim.x + threadIdx.x;
    if (idx >= BB * DD) return;
    int b = idx >> 9, d = idx & (DD - 1);
    const float* p = g_rbuf + (long long)b * NN * DD + d;
    float s = 0.f;
    for (int n = 0; n < NN; n++) s += p[(long long)n * DD];
    g_r[idx] = s * (1.f / (float)NN);
}

__global__ void gate_k(const float* __restrict__ Wg, const float* __restrict__ bg,
                       float* __restrict__ out_g) {
    __shared__ float lg[BB][EE];
    int tid = threadIdx.x;
    if (tid < BB * EE) {
        int b = tid >> 2, e = tid & 3;
        float s = bg[e];
        for (int k = 0; k < DD; k++) s = fmaf(g_r[b * DD + k], Wg[k * EE + e], s);
        lg[b][e] = s;
    }
    __syncthreads();
    if (tid < BB) {
        int b = tid;
        float mx = fmaxf(fmaxf(lg[b][0], lg[b][1]), fmaxf(lg[b][2], lg[b][3]));
        float ex[EE], s = 0.f;
        #pragma unroll
        for (int e = 0; e < EE; e++) { ex[e] = expf(lg[b][e] - mx); s += ex[e]; }
        #pragma unroll
        for (int e = 0; e < EE; e++) {
            float g = ex[e] / s;
            g_gs[b * EE + e] = g;
            out_g[b * EE + e] = g;
        }
    }
}

__global__ void mix_k(float* __restrict__ out_latent) {
    int idx = blockIdx.x * blockDim.x + threadIdx.x;
    if (idx >= BB * DD) return;
    int b = idx >> 9, d = idx & (DD - 1);
    float s = 0.f;
    #pragma unroll
    for (int e = 0; e < EE; e++)
        s = fmaf(g_gs[b * EE + e], g_lat[(e * BB + b) * DD + d], s);
    g_mixl[idx] = s;
    out_latent[idx] = s;
}

__global__ void head_k(const float* __restrict__ Wh1, const float* __restrict__ bh1,
                       const float* __restrict__ Wh2, const float* __restrict__ bh2,
                       float* __restrict__ out_logits) {
    __shared__ float hid[BB][64];
    int tid = threadIdx.x;
    {
        int b = tid >> 6, j = tid & 63;
        float s = bh1[j];
        for (int k = 0; k < DD; k++) s = fmaf(g_mixl[b * DD + k], Wh1[k * 64 + j], s);
        hid[b][j] = fmaxf(s, 0.f);
    }
    __syncthreads();
    if (tid < BB * NC) {
        int b = tid >> 2, c = tid & 3;
        float s = bh2[c];
        #pragma unroll
        for (int k = 0; k < 64; k++) s = fmaf(hid[b][k], Wh2[k * NC + c], s);
        out_logits[b * NC + c] = s;
    }
}

// =======================================================================
extern "C" void kernel_launch(void* const* d_in, const int* in_sizes, int n_in,
                              void* d_out, int out_size)
{
    const float* x     = (const float*)d_in[0];
    const float* Wp    = (const float*)d_in[1];
    const float* bp    = (const float*)d_in[2];
    const float* cls   = (const float*)d_in[3];
    const float* ln1_g = (const float*)d_in[4];
    const float* ln1_b = (const float*)d_in[5];
    const float* Wqkv  = (const float*)d_in[6];
    const float* bqkv  = (const float*)d_in[7];
    const float* Wo    = (const float*)d_in[8];
    const float* bo    = (const float*)d_in[9];
    const float* ln2_g = (const float*)d_in[10];
    const float* ln2_b = (const float*)d_in[11];
    const float* Wm1   = (const float*)d_in[12];
    const float* bm1   = (const float*)d_in[13];
    const float* Wm2   = (const float*)d_in[14];
    const float* bm2   = (const float*)d_in[15];
    const float* lnf_g = (const float*)d_in[16];
    const float* lnf_b = (const float*)d_in[17];
    const float* Wr    = (const float*)d_in[18];
    const float* br    = (const float*)d_in[19];
    const float* Wg    = (const float*)d_in[20];
    const float* bg    = (const float*)d_in[21];
    const float* Wh1   = (const float*)d_in[22];
    const float* bh1   = (const float*)d_in[23];
    const float* Wh2   = (const float*)d_in[24];
    const float* bh2   = (const float*)d_in[25];
    float* out = (float*)d_out;

    float *p_h, *p_qkv, *p_rbuf, *p_lat;
    __nv_bfloat16 *p_x3, *p_hn3, *p_ao3, *p_mlp3;
    __nv_bfloat16 *p_Wr3, *p_Wp3, *p_Wqkv3, *p_Wo3, *p_Wm13, *p_Wm23;
    cudaGetSymbolAddress((void**)&p_h,     g_h);
    cudaGetSymbolAddress((void**)&p_qkv,   g_qkv);
    cudaGetSymbolAddress((void**)&p_rbuf,  g_rbuf);
    cudaGetSymbolAddress((void**)&p_lat,   g_lat);
    cudaGetSymbolAddress((void**)&p_x3,    g_x3);
    cudaGetSymbolAddress((void**)&p_hn3,   g_hn3);
    cudaGetSymbolAddress((void**)&p_ao3,   g_ao3);
    cudaGetSymbolAddress((void**)&p_mlp3,  g_mlp3);
    cudaGetSymbolAddress((void**)&p_Wr3,   g_Wr3);
    cudaGetSymbolAddress((void**)&p_Wp3,   g_Wp3);
    cudaGetSymbolAddress((void**)&p_Wqkv3, g_Wqkv3);
    cudaGetSymbolAddress((void**)&p_Wo3,   g_Wo3);
    cudaGetSymbolAddress((void**)&p_Wm13,  g_Wm13);
    cudaGetSymbolAddress((void**)&p_Wm23,  g_Wm23);

    // opt-in to 64KB dynamic smem for all tgemm instantiations (host attr, capture-safe)
    const int SMEMSZ = 65536;
    cudaError_t attr_rc = cudaSuccess;
    attr_rc = cudaFuncSetAttribute(tgemm_k<1, false, false, false>,
                         cudaFuncAttributeMaxDynamicSharedMemorySize, SMEMSZ);
    attr_rc = cudaFuncSetAttribute(tgemm_k<0, true,  false, false>,
                         cudaFuncAttributeMaxDynamicSharedMemorySize, SMEMSZ);
    attr_rc = cudaFuncSetAttribute(tgemm_k<0, false, false, false>,
                         cudaFuncAttributeMaxDynamicSharedMemorySize, SMEMSZ);
    attr_rc = cudaFuncSetAttribute(tgemm_k<0, false, true,  false>,
                         cudaFuncAttributeMaxDynamicSharedMemorySize, SMEMSZ);
    attr_rc = cudaFuncSetAttribute(tgemm_k<2, false, false, true>,
                         cudaFuncAttributeMaxDynamicSharedMemorySize, SMEMSZ);
    (void)attr_rc;

    const long long sHD  = (long long)BS * DD;
    const long long sQKV = (long long)BS * 3 * DD;
    const long long sT   = (long long)BS * 3 * DD;
    dim3 wblk(32, 8);

    // Launch order: ncu profiles OUR launch #4 (2 harness pre-launches + -s 5).
    aconv_k<<<(int)(((long long)BB * NN * DIN + 255) / 256), 256>>>(        // 1
        x, p_x3, DIN, (long long)BB * NN * DIN);
    wconv_k<<<dim3(DD / 32, DIN / 32, 1), wblk>>>(Wr, p_Wr3, DIN, DD);      // 2
    cls_init_k<<<(EE * BB * DD + 255) / 256, 256>>>(cls);                   // 3
    tgemm_k<1, false, false, false><<<dim3(DD / 128, (BB * NN) / 128, 1), 256, SMEMSZ>>>(  // 4 (profiled)
        p_x3, p_Wr3, br, nullptr, p_rbuf, nullptr, BB * NN, DD, 3 * DIN,
        0, 0, 0, 0, 0, 0, 0);
    wconv_k<<<dim3(DD / 32, DIN / 32, EE), wblk>>>(Wp, p_Wp3, DIN, DD);     // 5
    tgemm_k<0, true, false, false><<<dim3(DD / 128, (BB * NN) / 128, EE), 256, SMEMSZ>>>(  // 6
        p_x3, p_Wp3, bp, nullptr, p_h, nullptr, BB * NN, DD, 3 * DIN,
        0, (long long)DD * 3 * DIN, DD, 0, sHD, NN, SS);

    router_reduce_k<<<(BB * DD + 255) / 256, 256>>>();
    gate_k<<<1, 64>>>(Wg, bg, out + BB * DD + BB * NC);

    wconv_k<<<dim3((3 * DD) / 32, DD / 32, EE * LL), wblk>>>(Wqkv, p_Wqkv3, DD, 3 * DD);
    wconv_k<<<dim3(DD / 32, DD / 32, EE * LL), wblk>>>(Wo, p_Wo3, DD, DD);
    wconv_k<<<dim3(MLPD / 32, DD / 32, EE * LL), wblk>>>(Wm1, p_Wm13, DD, MLPD);
    wconv_k<<<dim3(DD / 32, MLPD / 32, EE * LL), wblk>>>(Wm2, p_Wm23, MLPD, DD);

    // --- transformer layers ---
    const int gy = (BS + 127) / 128;   // 33
    for (int l = 0; l < LL; l++) {
        ln3_k<<<dim3(BS, EE), 128>>>(p_h, ln1_g + l * DD, ln1_b + l * DD, p_hn3,
                                     sHD, DD, sT, 3 * DD, (long long)LL * DD);
        tgemm_k<0, false, false, false><<<dim3((3 * DD) / 128, gy, EE), 256, SMEMSZ>>>(
            p_hn3, p_Wqkv3 + (long long)l * (3 * DD) * (3 * DD),
            bqkv + l * 3 * DD, nullptr, p_qkv, nullptr,
            BS, 3 * DD, 3 * DD,
            sT, (long long)LL * (3 * DD) * (3 * DD), (long long)LL * 3 * DD, 0, sQKV, 0, 0);
        attn_k<<<dim3((SS + 127) / 128, BB * HH, EE), 128>>>(SS);
        tgemm_k<0, false, true, false><<<dim3(DD / 128, gy, EE), 256, SMEMSZ>>>(
            p_ao3, p_Wo3 + (long long)l * DD * 3 * DD, bo + l * DD, p_h, p_h, nullptr,
            BS, DD, 3 * DD,
            sT, (long long)LL * DD * 3 * DD, (long long)LL * DD, sHD, sHD, 0, 0);
        ln3_k<<<dim3(BS, EE), 128>>>(p_h, ln2_g + l * DD, ln2_b + l * DD, p_hn3,
                                     sHD, DD, sT, 3 * DD, (long long)LL * DD);
        tgemm_k<2, false, false, true><<<dim3(MLPD / 128, gy, EE), 256, SMEMSZ>>>(
            p_hn3, p_Wm13 + (long long)l * MLPD * 3 * DD, bm1 + l * MLPD,
            nullptr, nullptr, p_mlp3,
            BS, MLPD, 3 * DD,
            sT, (long long)LL * MLPD * 3 * DD, (long long)LL * MLPD, 0,
            (long long)BS * 3 * MLPD, 0, 0);
        tgemm_k<0, false, true, false><<<dim3(DD / 128, gy, EE), 256, SMEMSZ>>>(
            p_mlp3, p_Wm23 + (long long)l * DD * 3 * MLPD, bm2 + l * DD, p_h, p_h, nullptr,
            BS, DD, 3 * MLPD,
            (long long)BS * 3 * MLPD, (long long)LL * DD * 3 * MLPD,
            (long long)LL * DD, sHD, sHD, 0, 0);
    }

    // --- final LN on cls rows -> latents [E,B,D] ---
    ln_k<<<dim3(BB, EE), 128>>>(p_h, lnf_g, lnf_b, p_lat,
                                sHD, (long long)SS * DD,
                                (long long)BB * DD, DD, DD);

    // --- mixture + head ---
    mix_k<<<(BB * DD + 255) / 256, 256>>>(out);
    head_k<<<1, 256>>>(Wh1, bh1, Wh2, bh2, out + BB * DD);
}

// round 16
// speedup vs baseline: 1.2254x; 1.2254x over previous
#include <cuda_runtime.h>
#include <cuda_bf16.h>
#include <cstdint>
#include <math.h>

#define EE   4
#define LL   2
#define BB   4
#define NN   1024
#define SS   1025
#define DIN  2048
#define DD   512
#define HH   8
#define DHD  64
#define MLPD 512
#define NC   4
#define BS   (BB*SS)        // 4100
#define SP   1152           // padded sequence (9*128)
#define SP3  (3*SP)         // 3456
#define KQ   192            // 3*DHD
#define ZB   32             // (b,h) pairs per expert shard

// ---------------- scratch (device globals) ----------------
__device__ float g_h   [(size_t)EE*BS*DD];
__device__ float g_qkv [(size_t)EE*BS*3*DD];
__device__ float g_rbuf[(size_t)BB*NN*DD];
__device__ float g_r   [BB*DD];
__device__ float g_gs  [BB*EE];
__device__ float g_lat [EE*BB*DD];
__device__ float g_mixl[BB*DD];
// bf16 triplet activations (A side: hi,hi,lo -> width 3K)
__device__ __nv_bfloat16 g_x3  [(size_t)BB*NN*3*DIN];
__device__ __nv_bfloat16 g_hn3 [(size_t)EE*BS*3*DD];
__device__ __nv_bfloat16 g_ao3 [(size_t)EE*BS*3*DD];
__device__ __nv_bfloat16 g_mlp3[(size_t)EE*BS*3*MLPD];
// bf16 triplet weights (B side: [N,3K], hi,lo,hi)
__device__ __nv_bfloat16 g_Wr3  [(size_t)DD*3*DIN];
__device__ __nv_bfloat16 g_Wp3  [(size_t)EE*DD*3*DIN];
__device__ __nv_bfloat16 g_Wqkv3[(size_t)EE*LL*(3*DD)*(3*DD)];
__device__ __nv_bfloat16 g_Wo3  [(size_t)EE*LL*DD*(3*DD)];
__device__ __nv_bfloat16 g_Wm13 [(size_t)EE*LL*MLPD*(3*DD)];
__device__ __nv_bfloat16 g_Wm23 [(size_t)EE*LL*DD*(3*MLPD)];
// tensor-attention buffers, per-expert shard of ZB=32 (b,h) pairs
__device__ __nv_bfloat16 g_Q3[(size_t)ZB*SP*KQ];
__device__ __nv_bfloat16 g_K3[(size_t)ZB*SP*KQ];
__device__ float         g_S [(size_t)ZB*SP*SP];
__device__ __nv_bfloat16 g_P3[(size_t)ZB*SP*SP3];
__device__ __nv_bfloat16 g_V3[(size_t)ZB*DHD*SP3];

// ---------------- helpers ----------------
__device__ __forceinline__ uint32_t smem_u32(const void* p) {
    uint32_t a;
    asm("{ .reg .u64 t; cvta.to.shared.u64 t, %1; cvt.u32.u64 %0, t; }" : "=r"(a) : "l"(p));
    return a;
}
#define SW128(off) ((off) ^ (((off) >> 3) & 0x70))

__device__ __forceinline__ void ldm_x4(uint32_t* r, uint32_t addr) {
    asm volatile("ldmatrix.sync.aligned.m8n8.x4.shared.b16 {%0,%1,%2,%3}, [%4];"
        : "=r"(r[0]), "=r"(r[1]), "=r"(r[2]), "=r"(r[3]) : "r"(addr));
}
__device__ __forceinline__ void mma16816(float* d, const uint32_t* a, const uint32_t* b) {
    asm volatile("mma.sync.aligned.m16n8k16.row.col.f32.bf16.bf16.f32 "
        "{%0,%1,%2,%3}, {%4,%5,%6,%7}, {%8,%9}, {%0,%1,%2,%3};"
        : "+f"(d[0]), "+f"(d[1]), "+f"(d[2]), "+f"(d[3])
        : "r"(a[0]), "r"(a[1]), "r"(a[2]), "r"(a[3]), "r"(b[0]), "r"(b[1]));
}
__device__ __forceinline__ void cp16(uint32_t dst, const void* src, int bytes) {
    asm volatile("cp.async.cg.shared.global [%0], [%1], 16, %2;"
        :: "r"(dst), "l"(src), "r"(bytes));
}
#define CP_COMMIT() asm volatile("cp.async.commit_group;" ::: "memory")
#define CP_WAIT1()  asm volatile("cp.async.wait_group 1;" ::: "memory")
#define CP_WAIT0()  asm volatile("cp.async.wait_group 0;" ::: "memory")

__device__ __forceinline__ float gelu_tanh(float x) {
    float x3 = x * x * x;
    float t  = tanhf(0.7978845608028654f * (x + 0.044715f * x3));
    return 0.5f * x * (1.0f + t);
}
__device__ __forceinline__ void split2(float v, __nv_bfloat16& hi, __nv_bfloat16& lo) {
    hi = __float2bfloat16(v);
    lo = __float2bfloat16(v - __bfloat162float(hi));
}
__device__ __forceinline__ float blockReduceSum(float v) {
    __shared__ float sh[32];
    int lane = threadIdx.x & 31, wid = threadIdx.x >> 5;
    #pragma unroll
    for (int o = 16; o > 0; o >>= 1) v += __shfl_xor_sync(0xffffffffu, v, o);
    if (lane == 0) sh[wid] = v;
    __syncthreads();
    int nw = (blockDim.x + 31) >> 5;
    if (wid == 0) {
        float t = (lane < nw) ? sh[lane] : 0.f;
        #pragma unroll
        for (int o = 16; o > 0; o >>= 1) t += __shfl_xor_sync(0xffffffffu, t, o);
        if (lane == 0) sh[0] = t;
    }
    __syncthreads();
    float r = sh[0];
    __syncthreads();
    return r;
}
__device__ __forceinline__ float blockReduceMax(float v) {
    __shared__ float sh[32];
    int lane = threadIdx.x & 31, wid = threadIdx.x >> 5;
    #pragma unroll
    for (int o = 16; o > 0; o >>= 1) v = fmaxf(v, __shfl_xor_sync(0xffffffffu, v, o));
    if (lane == 0) sh[wid] = v;
    __syncthreads();
    int nw = (blockDim.x + 31) >> 5;
    if (wid == 0) {
        float t = (lane < nw) ? sh[lane] : -1e30f;
        #pragma unroll
        for (int o = 16; o > 0; o >>= 1) t = fmaxf(t, __shfl_xor_sync(0xffffffffu, t, o));
        if (lane == 0) sh[0] = t;
    }
    __syncthreads();
    float r = sh[0];
    __syncthreads();
    return r;
}

// =======================================================================
// main tgemm: 128x128 tile, cp.async double-buffer, dynamic smem 64KB
// =======================================================================
template <int ACT, bool REMAP, bool HASRES, bool OUTTRIP>
__global__ __launch_bounds__(256) void tgemm_k(
    const __nv_bfloat16* __restrict__ A3, const __nv_bfloat16* __restrict__ B3,
    const float* __restrict__ bias, const float* __restrict__ Res,
    float* __restrict__ Cf, __nv_bfloat16* __restrict__ Ct,
    int M, int N, int Kp,
    long long sA, long long sB, long long sBias, long long sRes, long long sC,
    int mapN, int mapS)
{
    extern __shared__ __align__(128) char smem[];
    const int tid = threadIdx.x, wid = tid >> 5, lane = tid & 31;
    const long long e = blockIdx.z;
    A3 += e * sA; B3 += e * sB; bias += e * sBias;
    const int brow = blockIdx.y * 128, bcol = blockIdx.x * 128;
    const int wm = wid >> 2, wn = wid & 3;

    float acc[4][4][4];
    #pragma unroll
    for (int i = 0; i < 4; i++)
        #pragma unroll
        for (int j = 0; j < 4; j++)
            #pragma unroll
            for (int f = 0; f < 4; f++) acc[i][j][f] = 0.f;

    const uint32_t sbase = smem_u32(smem);
    const uint32_t sa[2]  = { sbase, sbase + 16384 };
    const uint32_t sbm[2] = { sbase + 32768, sbase + 49152 };

    const int baseRow = tid >> 3;
    const int cb = (tid & 7) * 16;
    uint32_t swoff[4];
    int aok[4]; long long arow[4], browi[4];
    #pragma unroll
    for (int p = 0; p < 4; p++) {
        int row = baseRow + 32 * p;
        swoff[p] = SW128((uint32_t)(row * 128 + cb));
        int gr = brow + row;
        aok[p]  = (gr < M) ? 16 : 0;
        arow[p] = (gr < M) ? gr : (M - 1);
        browi[p] = bcol + row;
    }
    const int NCk = Kp >> 6;

    #pragma unroll
    for (int p = 0; p < 4; p++) {
        cp16(sa[0]  + swoff[p], (const char*)(A3 + arow[p]  * Kp) + cb, aok[p]);
        cp16(sbm[0] + swoff[p], (const char*)(B3 + browi[p] * Kp) + cb, 16);
    }
    CP_COMMIT();

    for (int c = 0; c < NCk; c++) {
        const int buf = c & 1;
        if (c + 1 < NCk) {
            const int nb = buf ^ 1;
            #pragma unroll
            for (int p = 0; p < 4; p++) {
                cp16(sa[nb]  + swoff[p],
                     (const char*)(A3 + arow[p]  * Kp + (c + 1) * 64) + cb, aok[p]);
                cp16(sbm[nb] + swoff[p],
                     (const char*)(B3 + browi[p] * Kp + (c + 1) * 64) + cb, 16);
            }
            CP_COMMIT();
            CP_WAIT1();
        } else {
            CP_WAIT0();
        }
        __syncthreads();

        const uint32_t asb = sa[buf], bsb = sbm[buf];
        #pragma unroll
        for (int ks = 0; ks < 4; ks++) {
            uint32_t afr[4][4], bfr[2][4];
            #pragma unroll
            for (int mi = 0; mi < 4; mi++) {
                int ar = wm * 64 + mi * 16 + (lane & 15);
                int ac = ks * 32 + (lane >> 4) * 16;
                ldm_x4(afr[mi], asb + SW128((uint32_t)(ar * 128 + ac)));
            }
            #pragma unroll
            for (int np = 0; np < 2; np++) {
                int nr = wn * 32 + np * 16 + (lane & 7) + ((lane >> 4) & 1) * 8;
                int bc = ks * 32 + ((lane >> 3) & 1) * 16;
                ldm_x4(bfr[np], bsb + SW128((uint32_t)(nr * 128 + bc)));
            }
            #pragma unroll
            for (int mi = 0; mi < 4; mi++)
                #pragma unroll
                for (int ni = 0; ni < 4; ni++)
                    mma16816(acc[mi][ni], afr[mi], &bfr[ni >> 1][(ni & 1) * 2]);
        }
        __syncthreads();
    }

    #pragma unroll
    for (int mi = 0; mi < 4; mi++) {
        #pragma unroll
        for (int half = 0; half < 2; half++) {
            int row = brow + wm * 64 + mi * 16 + (lane >> 2) + half * 8;
            if (row >= M) continue;
            long long orow = row;
            if (REMAP) orow = (long long)(row / mapN) * mapS + 1 + (row % mapN);
            #pragma unroll
            for (int ni = 0; ni < 4; ni++) {
                int col = bcol + wn * 32 + ni * 8 + (lane & 3) * 2;
                float v0 = acc[mi][ni][half * 2 + 0] + bias[col];
                float v1 = acc[mi][ni][half * 2 + 1] + bias[col + 1];
                if (HASRES) {
                    float2 rr = *(const float2*)(Res + e * sRes + orow * (long long)N + col);
                    v0 += rr.x; v1 += rr.y;
                }
                if (ACT == 1) { v0 = fmaxf(v0, 0.f); v1 = fmaxf(v1, 0.f); }
                else if (ACT == 2) { v0 = gelu_tanh(v0); v1 = gelu_tanh(v1); }
                if (OUTTRIP) {
                    __nv_bfloat16* op = Ct + e * sC + orow * (long long)(3 * N) + 3 * col;
                    __nv_bfloat16 h0, l0, h1, l1;
                    split2(v0, h0, l0); split2(v1, h1, l1);
                    op[0] = h0; op[1] = h0; op[2] = l0;
                    op[3] = h1; op[4] = h1; op[5] = l1;
                } else {
                    float* cp = Cf + e * sC + orow * (long long)N + col;
                    *(float2*)cp = make_float2(v0, v1);
                }
            }
        }
    }
}

// =======================================================================
// tscore_k: S[zl][q][k] = 0.125 * Q3[zl] . K3[zl]^T ; grid (9,9,ZB)
// =======================================================================
__global__ __launch_bounds__(256) void tscore_k()
{
    extern __shared__ __align__(128) char smem[];
    const int tid = threadIdx.x, wid = tid >> 5, lane = tid & 31;
    const long long z = blockIdx.z;
    const __nv_bfloat16* A3 = g_Q3 + z * (long long)SP * KQ;
    const __nv_bfloat16* B3 = g_K3 + z * (long long)SP * KQ;
    float* Cf = g_S + z * (long long)SP * SP;
    const int brow = blockIdx.y * 128, bcol = blockIdx.x * 128;
    const int wm = wid >> 2, wn = wid & 3;

    float acc[4][4][4];
    #pragma unroll
    for (int i = 0; i < 4; i++)
        #pragma unroll
        for (int j = 0; j < 4; j++)
            #pragma unroll
            for (int f = 0; f < 4; f++) acc[i][j][f] = 0.f;

    const uint32_t sbase = smem_u32(smem);
    const uint32_t sa[2]  = { sbase, sbase + 16384 };
    const uint32_t sbm[2] = { sbase + 32768, sbase + 49152 };

    const int baseRow = tid >> 3;
    const int cb = (tid & 7) * 16;
    uint32_t swoff[4];
    long long arow[4], browi[4];
    #pragma unroll
    for (int p = 0; p < 4; p++) {
        int row = baseRow + 32 * p;
        swoff[p] = SW128((uint32_t)(row * 128 + cb));
        arow[p]  = brow + row;
        browi[p] = bcol + row;
    }

    #pragma unroll
    for (int p = 0; p < 4; p++) {
        cp16(sa[0]  + swoff[p], (const char*)(A3 + arow[p]  * KQ) + cb, 16);
        cp16(sbm[0] + swoff[p], (const char*)(B3 + browi[p] * KQ) + cb, 16);
    }
    CP_COMMIT();

    for (int c = 0; c < 3; c++) {
        const int buf = c & 1;
        if (c + 1 < 3) {
            const int nb = buf ^ 1;
            #pragma unroll
            for (int p = 0; p < 4; p++) {
                cp16(sa[nb]  + swoff[p],
                     (const char*)(A3 + arow[p]  * KQ + (c + 1) * 64) + cb, 16);
                cp16(sbm[nb] + swoff[p],
                     (const char*)(B3 + browi[p] * KQ + (c + 1) * 64) + cb, 16);
            }
            CP_COMMIT();
            CP_WAIT1();
        } else {
            CP_WAIT0();
        }
        __syncthreads();

        const uint32_t asb = sa[buf], bsb = sbm[buf];
        #pragma unroll
        for (int ks = 0; ks < 4; ks++) {
            uint32_t afr[4][4], bfr[2][4];
            #pragma unroll
            for (int mi = 0; mi < 4; mi++) {
                int ar = wm * 64 + mi * 16 + (lane & 15);
                int ac = ks * 32 + (lane >> 4) * 16;
                ldm_x4(afr[mi], asb + SW128((uint32_t)(ar * 128 + ac)));
            }
            #pragma unroll
            for (int np = 0; np < 2; np++) {
                int nr = wn * 32 + np * 16 + (lane & 7) + ((lane >> 4) & 1) * 8;
                int bc = ks * 32 + ((lane >> 3) & 1) * 16;
                ldm_x4(bfr[np], bsb + SW128((uint32_t)(nr * 128 + bc)));
            }
            #pragma unroll
            for (int mi = 0; mi < 4; mi++)
                #pragma unroll
                for (int ni = 0; ni < 4; ni++)
                    mma16816(acc[mi][ni], afr[mi], &bfr[ni >> 1][(ni & 1) * 2]);
        }
        __syncthreads();
    }

    #pragma unroll
    for (int mi = 0; mi < 4; mi++) {
        #pragma unroll
        for (int half = 0; half < 2; half++) {
            int row = brow + wm * 64 + mi * 16 + (lane >> 2) + half * 8;
            #pragma unroll
            for (int ni = 0; ni < 4; ni++) {
                int col = bcol + wn * 32 + ni * 8 + (lane & 3) * 2;
                float v0 = acc[mi][ni][half * 2 + 0] * 0.125f;
                float v1 = acc[mi][ni][half * 2 + 1] * 0.125f;
                *(float2*)(Cf + (long long)row * SP + col) = make_float2(v0, v1);
            }
        }
    }
}

// =======================================================================
// tav_k: O[zl] = P3[zl] . V3[zl]^T ; 128x64 tile (static 48KB), Kp=SP3
// grid (1, 9, ZB); eo = expert index; triplet epilogue into g_ao3
// =======================================================================
__global__ __launch_bounds__(256) void tav_k(int eo)
{
    __shared__ __align__(128) char SA[2][128 * 128];
    __shared__ __align__(128) char SB[2][64 * 128];
    const int tid = threadIdx.x, wid = tid >> 5, lane = tid & 31;
    const int zl = blockIdx.z;
    const int b = (zl >> 3) & 3, h = zl & 7;
    const __nv_bfloat16* A3 = g_P3 + (long long)zl * SP * SP3;
    const __nv_bfloat16* B3 = g_V3 + (long long)zl * DHD * SP3;
    const int brow = blockIdx.y * 128;
    const int wm = wid >> 1, wn = wid & 1;

    float acc[2][4][4];
    #pragma unroll
    for (int i = 0; i < 2; i++)
        #pragma unroll
        for (int j = 0; j < 4; j++)
            #pragma unroll
            for (int f = 0; f < 4; f++) acc[i][j][f] = 0.f;

    const uint32_t sa[2]  = { smem_u32(SA[0]), smem_u32(SA[1]) };
    const uint32_t sbm[2] = { smem_u32(SB[0]), smem_u32(SB[1]) };

    const int baseRow = tid >> 3;
    const int cb = (tid & 7) * 16;
    uint32_t swoff[4];
    int aok[4]; long long arow[4];
    #pragma unroll
    for (int p = 0; p < 4; p++) {
        int row = baseRow + 32 * p;
        swoff[p] = SW128((uint32_t)(row * 128 + cb));
        int gr = brow + row;
        aok[p]  = (gr < SS) ? 16 : 0;
        arow[p] = (gr < SS) ? gr : (SS - 1);
    }
    long long browi[2] = { baseRow, baseRow + 32 };
    const int NCk = SP3 >> 6;    // 54

    #pragma unroll
    for (int p = 0; p < 4; p++)
        cp16(sa[0] + swoff[p], (const char*)(A3 + arow[p] * SP3) + cb, aok[p]);
    #pragma unroll
    for (int p = 0; p < 2; p++)
        cp16(sbm[0] + swoff[p], (const char*)(B3 + browi[p] * SP3) + cb, 16);
    CP_COMMIT();

    for (int c = 0; c < NCk; c++) {
        const int buf = c & 1;
        if (c + 1 < NCk) {
            const int nb = buf ^ 1;
            #pragma unroll
            for (int p = 0; p < 4; p++)
                cp16(sa[nb] + swoff[p],
                     (const char*)(A3 + arow[p] * SP3 + (c + 1) * 64) + cb, aok[p]);
            #pragma unroll
            for (int p = 0; p < 2; p++)
                cp16(sbm[nb] + swoff[p],
                     (const char*)(B3 + browi[p] * SP3 + (c + 1) * 64) + cb, 16);
            CP_COMMIT();
            CP_WAIT1();
        } else {
            CP_WAIT0();
        }
        __syncthreads();

        const uint32_t asb = sa[buf], bsb = sbm[buf];
        #pragma unroll
        for (int ks = 0; ks < 4; ks++) {
            uint32_t afr[2][4], bfr[2][4];
            #pragma unroll
            for (int mi = 0; mi < 2; mi++) {
                int ar = wm * 32 + mi * 16 + (lane & 15);
                int ac = ks * 32 + (lane >> 4) * 16;
                ldm_x4(afr[mi], asb + SW128((uint32_t)(ar * 128 + ac)));
            }
            #pragma unroll
            for (int np = 0; np < 2; np++) {
                int nr = wn * 32 + np * 16 + (lane & 7) + ((lane >> 4) & 1) * 8;
                int bc = ks * 32 + ((lane >> 3) & 1) * 16;
                ldm_x4(bfr[np], bsb + SW128((uint32_t)(nr * 128 + bc)));
            }
            #pragma unroll
            for (int mi = 0; mi < 2; mi++)
                #pragma unroll
                for (int ni = 0; ni < 4; ni++)
                    mma16816(acc[mi][ni], afr[mi], &bfr[ni >> 1][(ni & 1) * 2]);
        }
        __syncthreads();
    }

    #pragma unroll
    for (int mi = 0; mi < 2; mi++) {
        #pragma unroll
        for (int half = 0; half < 2; half++) {
            int row = brow + wm * 32 + mi * 16 + (lane >> 2) + half * 8;
            if (row >= SS) continue;
            __nv_bfloat16* op = g_ao3 +
                ((long long)(eo * BS + b * SS) + row) * (3 * DD) + 3 * (h * DHD);
            #pragma unroll
            for (int ni = 0; ni < 4; ni++) {
                int col = wn * 32 + ni * 8 + (lane & 3) * 2;
                float v0 = acc[mi][ni][half * 2 + 0];
                float v1 = acc[mi][ni][half * 2 + 1];
                __nv_bfloat16 h0, l0, h1, l1;
                split2(v0, h0, l0); split2(v1, h1, l1);
                op[3 * col]     = h0; op[3 * col + 1] = h0; op[3 * col + 2] = l0;
                op[3 * col + 3] = h1; op[3 * col + 4] = h1; op[3 * col + 5] = l1;
            }
        }
    }
}

// ---------------- attention conversions (per-expert shard) ----------------
// Q/K -> triplets, padded rows zero. grid (SP, ZB), block 64.
__global__ void qk3conv_k(int eo) {
    const int row = blockIdx.x, zl = blockIdx.y, d = threadIdx.x;
    const int b = (zl >> 3) & 3, h = zl & 7;
    float qv = 0.f, kv = 0.f;
    if (row < SS) {
        const float* p = g_qkv + (((long long)eo * BS + b * SS + row) * 3 * DD) + h * DHD + d;
        qv = p[0]; kv = p[DD];
    }
    __nv_bfloat16 qh, ql, kh, kl;
    split2(qv, qh, ql); split2(kv, kh, kl);
    long long base = ((long long)zl * SP + row) * KQ + 3 * d;
    g_Q3[base] = qh; g_Q3[base + 1] = qh; g_Q3[base + 2] = ql;
    g_K3[base] = kh; g_K3[base + 1] = kl; g_K3[base + 2] = kh;
}

// V -> Vt3 [d][3k] (hi,lo,hi) via smem transpose. grid (SP/64, ZB), block 64.
__global__ void vt3conv_k(int eo) {
    __shared__ float sm[64][65];
    const int k0 = blockIdx.x * 64, zl = blockIdx.y, t = threadIdx.x;
    const int b = (zl >> 3) & 3, h = zl & 7;
    for (int i = 0; i < 64; i++) {
        int k = k0 + i;
        sm[t][i] = (k < SS)
            ? g_qkv[(((long long)eo * BS + b * SS + k) * 3 * DD) + 2 * DD + h * DHD + t]
            : 0.f;
    }
    __syncthreads();
    __nv_bfloat16* op = g_V3 + ((long long)zl * DHD + t) * SP3 + 3 * k0;
    for (int i = 0; i < 64; i++) {
        __nv_bfloat16 hi, lo; split2(sm[t][i], hi, lo);
        op[3 * i] = hi; op[3 * i + 1] = lo; op[3 * i + 2] = hi;
    }
}

// softmax rows of S -> P3 triplets (hi,hi,lo), padded cols zero.
// grid (SS, ZB), block 128.
__global__ __launch_bounds__(128) void softp3_k() {
    __shared__ float se[1028];
    const int q = blockIdx.x, zl = blockIdx.y, tid = threadIdx.x;
    const float* s = g_S + ((long long)zl * SP + q) * SP;
    float mx = -1e30f;
    for (int k = tid; k < SS; k += 128) mx = fmaxf(mx, s[k]);
    mx = blockReduceMax(mx);
    float sum = 0.f;
    for (int k = tid; k < SS; k += 128) {
        float ev = __expf(s[k] - mx);
        se[k] = ev;
        sum += ev;
    }
    sum = blockReduceSum(sum);
    const float inv = 1.f / sum;
    __nv_bfloat16* p = g_P3 + ((long long)zl * SP + q) * SP3;
    __syncthreads();
    for (int k = tid; k < SS; k += 128) {
        __nv_bfloat16 hi, lo; split2(se[k] * inv, hi, lo);
        p[3 * k] = hi; p[3 * k + 1] = hi; p[3 * k + 2] = lo;
    }
    const __nv_bfloat16 zz = __float2bfloat16(0.f);
    for (int k = SS + tid; k < SP; k += 128) {
        p[3 * k] = zz; p[3 * k + 1] = zz; p[3 * k + 2] = zz;
    }
}

// ---------------- existing conversions ----------------
__global__ void aconv_k(const float* __restrict__ X, __nv_bfloat16* __restrict__ X3,
                        int Kdim, long long total)
{
    long long idx = (long long)blockIdx.x * blockDim.x + threadIdx.x;
    if (idx >= total) return;
    long long m = idx / Kdim;
    int k = (int)(idx - m * Kdim);
    __nv_bfloat16 hi, lo; split2(X[idx], hi, lo);
    long long base = m * (long long)(3 * Kdim) + 3 * k;
    X3[base] = hi; X3[base + 1] = hi; X3[base + 2] = lo;
}

__global__ void wconv_k(const float* __restrict__ W, __nv_bfloat16* __restrict__ W3,
                        int K, int N)
{
    __shared__ float t[32][33];
    const int n0 = blockIdx.x * 32, k0 = blockIdx.y * 32;
    const float* Wb = W + (long long)blockIdx.z * K * N;
    __nv_bfloat16* Ob = W3 + (long long)blockIdx.z * N * 3 * K;
    const int tx = threadIdx.x, ty = threadIdx.y;
    for (int i = ty; i < 32; i += 8)
        t[i][tx] = Wb[(long long)(k0 + i) * N + n0 + tx];
    __syncthreads();
    for (int i = ty; i < 32; i += 8) {
        int n = n0 + i;
        __nv_bfloat16 hi, lo; split2(t[tx][i], hi, lo);
        long long base = (long long)n * 3 * K + 3 * (k0 + tx);
        Ob[base] = hi; Ob[base + 1] = lo; Ob[base + 2] = hi;
    }
}

// ---------------- LayerNorms ----------------
__global__ __launch_bounds__(128) void ln3_k(
    const float* __restrict__ X, const float* __restrict__ G,
    const float* __restrict__ Bt, __nv_bfloat16* __restrict__ Y3,
    long long xb, long long xr, long long yb, long long yr, long long gs)
{
    const long long e = blockIdx.y;
    const float* x = X + e * xb + (long long)blockIdx.x * xr;
    __nv_bfloat16* y = Y3 + e * yb + (long long)blockIdx.x * yr;
    const float* g = G + e * gs;
    const float* b = Bt + e * gs;
    const int tid = threadIdx.x;

    float4 v = *(const float4*)(x + tid * 4);
    float s = blockReduceSum(v.x + v.y + v.z + v.w);
    float mean = s * (1.f / 512.f);
    float dx = v.x - mean, dy = v.y - mean, dz = v.z - mean, dw = v.w - mean;
    float s2 = blockReduceSum(dx * dx + dy * dy + dz * dz + dw * dw);
    float rstd = rsqrtf(s2 * (1.f / 512.f) + 1e-5f);
    float4 gv = *(const float4*)(g + tid * 4);
    float4 bv = *(const float4*)(b + tid * 4);
    float o[4] = { dx * rstd * gv.x + bv.x, dy * rstd * gv.y + bv.y,
                   dz * rstd * gv.z + bv.z, dw * rstd * gv.w + bv.w };
    #pragma unroll
    for (int j = 0; j < 4; j++) {
        __nv_bfloat16 hi, lo; split2(o[j], hi, lo);
        long long base = 3 * (long long)(tid * 4 + j);
        y[base] = hi; y[base + 1] = hi; y[base + 2] = lo;
    }
}

__global__ __launch_bounds__(128) void ln_k(
    const float* __restrict__ X, const float* __restrict__ G,
    const float* __restrict__ Bt, float* __restrict__ Y,
    long long xb, long long xr, long long yb, long long yr, long long gs)
{
    const long long e = blockIdx.y;
    const float* x = X + e * xb + (long long)blockIdx.x * xr;
    float*       y = Y + e * yb + (long long)blockIdx.x * yr;
    const float* g = G + e * gs;
    const float* b = Bt + e * gs;
    const int tid = threadIdx.x;

    float4 v = *(const float4*)(x + tid * 4);
    float s = blockReduceSum(v.x + v.y + v.z + v.w);
    float mean = s * (1.f / 512.f);
    float dx = v.x - mean, dy = v.y - mean, dz = v.z - mean, dw = v.w - mean;
    float s2 = blockReduceSum(dx * dx + dy * dy + dz * dz + dw * dw);
    float rstd = rsqrtf(s2 * (1.f / 512.f) + 1e-5f);
    float4 gv = *(const float4*)(g + tid * 4);
    float4 bv = *(const float4*)(b + tid * 4);
    float4 o;
    o.x = dx * rstd * gv.x + bv.x;
    o.y = dy * rstd * gv.y + bv.y;
    o.z = dz * rstd * gv.z + bv.z;
    o.w = dw * rstd * gv.w + bv.w;
    *(float4*)(y + tid * 4) = o;
}

__global__ void cls_init_k(const float* __restrict__ cls) {
    int idx = blockIdx.x * blockDim.x + threadIdx.x;
    if (idx >= EE * BB * DD) return;
    int d = idx & (DD - 1);
    int r = idx >> 9;
    int b = r & (BB - 1);
    int e = r >> 2;
    g_h[((long long)e * BS + (long long)b * SS) * DD + d] = cls[e * DD + d];
}

// ---------------- router / gate / mix / head ----------------
__global__ void router_reduce_k() {
    int idx = blockIdx.x * blockDim.x + threadIdx.x;
    if (idx >= BB * DD) return;
    int b = idx >> 9, d = idx & (DD - 1);
    const float* p = g_rbuf + (long long)b * NN * DD + d;
    float s = 0.f;
    for (int n = 0; n < NN; n++) s += p[(long long)n * DD];
    g_r[idx] = s * (1.f / (float)NN);
}

__global__ void gate_k(const float* __restrict__ Wg, const float* __restrict__ bg,
                       float* __restrict__ out_g) {
    __shared__ float lg[BB][EE];
    int tid = threadIdx.x;
    if (tid < BB * EE) {
        int b = tid >> 2, e = tid & 3;
        float s = bg[e];
        for (int k = 0; k < DD; k++) s = fmaf(g_r[b * DD + k], Wg[k * EE + e], s);
        lg[b][e] = s;
    }
    __syncthreads();
    if (tid < BB) {
        int b = tid;
        float mx = fmaxf(fmaxf(lg[b][0], lg[b][1]), fmaxf(lg[b][2], lg[b][3]));
        float ex[EE], s = 0.f;
        #pragma unroll
        for (int e = 0; e < EE; e++) { ex[e] = expf(lg[b][e] - mx); s += ex[e]; }
        #pragma unroll
        for (int e = 0; e < EE; e++) {
            float g = ex[e] / s;
            g_gs[b * EE + e] = g;
            out_g[b * EE + e] = g;
        }
    }
}

__global__ void mix_k(float* __restrict__ out_latent) {
    int idx = blockIdx.x * blockDim.x + threadIdx.x;
    if (idx >= BB * DD) return;
    int b = idx >> 9, d = idx & (DD - 1);
    float s = 0.f;
    #pragma unroll
    for (int e = 0; e < EE; e++)
        s = fmaf(g_gs[b * EE + e], g_lat[(e * BB + b) * DD + d], s);
    g_mixl[idx] = s;
    out_latent[idx] = s;
}

__global__ void head_k(const float* __restrict__ Wh1, const float* __restrict__ bh1,
                       const float* __restrict__ Wh2, const float* __restrict__ bh2,
                       float* __restrict__ out_logits) {
    __shared__ float hid[BB][64];
    int tid = threadIdx.x;
    {
        int b = tid >> 6, j = tid & 63;
        float s = bh1[j];
        for (int k = 0; k < DD; k++) s = fmaf(g_mixl[b * DD + k], Wh1[k * 64 + j], s);
        hid[b][j] = fmaxf(s, 0.f);
    }
    __syncthreads();
    if (tid < BB * NC) {
        int b = tid >> 2, c = tid & 3;
        float s = bh2[c];
        #pragma unroll
        for (int k = 0; k < 64; k++) s = fmaf(hid[b][k], Wh2[k * NC + c], s);
        out_logits[b * NC + c] = s;
    }
}

// =======================================================================
extern "C" void kernel_launch(void* const* d_in, const int* in_sizes, int n_in,
                              void* d_out, int out_size)
{
    const float* x     = (const float*)d_in[0];
    const float* Wp    = (const float*)d_in[1];
    const float* bp    = (const float*)d_in[2];
    const float* cls   = (const float*)d_in[3];
    const float* ln1_g = (const float*)d_in[4];
    const float* ln1_b = (const float*)d_in[5];
    const float* Wqkv  = (const float*)d_in[6];
    const float* bqkv  = (const float*)d_in[7];
    const float* Wo    = (const float*)d_in[8];
    const float* bo    = (const float*)d_in[9];
    const float* ln2_g = (const float*)d_in[10];
    const float* ln2_b = (const float*)d_in[11];
    const float* Wm1   = (const float*)d_in[12];
    const float* bm1   = (const float*)d_in[13];
    const float* Wm2   = (const float*)d_in[14];
    const float* bm2   = (const float*)d_in[15];
    const float* lnf_g = (const float*)d_in[16];
    const float* lnf_b = (const float*)d_in[17];
    const float* Wr    = (const float*)d_in[18];
    const float* br    = (const float*)d_in[19];
    const float* Wg    = (const float*)d_in[20];
    const float* bg    = (const float*)d_in[21];
    const float* Wh1   = (const float*)d_in[22];
    const float* bh1   = (const float*)d_in[23];
    const float* Wh2   = (const float*)d_in[24];
    const float* bh2   = (const float*)d_in[25];
    float* out = (float*)d_out;

    float *p_h, *p_qkv, *p_rbuf, *p_lat;
    __nv_bfloat16 *p_x3, *p_hn3, *p_ao3, *p_mlp3;
    __nv_bfloat16 *p_Wr3, *p_Wp3, *p_Wqkv3, *p_Wo3, *p_Wm13, *p_Wm23;
    cudaGetSymbolAddress((void**)&p_h,     g_h);
    cudaGetSymbolAddress((void**)&p_qkv,   g_qkv);
    cudaGetSymbolAddress((void**)&p_rbuf,  g_rbuf);
    cudaGetSymbolAddress((void**)&p_lat,   g_lat);
    cudaGetSymbolAddress((void**)&p_x3,    g_x3);
    cudaGetSymbolAddress((void**)&p_hn3,   g_hn3);
    cudaGetSymbolAddress((void**)&p_ao3,   g_ao3);
    cudaGetSymbolAddress((void**)&p_mlp3,  g_mlp3);
    cudaGetSymbolAddress((void**)&p_Wr3,   g_Wr3);
    cudaGetSymbolAddress((void**)&p_Wp3,   g_Wp3);
    cudaGetSymbolAddress((void**)&p_Wqkv3, g_Wqkv3);
    cudaGetSymbolAddress((void**)&p_Wo3,   g_Wo3);
    cudaGetSymbolAddress((void**)&p_Wm13,  g_Wm13);
    cudaGetSymbolAddress((void**)&p_Wm23,  g_Wm23);

    const int SMEMSZ = 65536;
    cudaError_t attr_rc = cudaSuccess;
    attr_rc = cudaFuncSetAttribute(tgemm_k<1, false, false, false>,
                         cudaFuncAttributeMaxDynamicSharedMemorySize, SMEMSZ);
    attr_rc = cudaFuncSetAttribute(tgemm_k<0, true,  false, false>,
                         cudaFuncAttributeMaxDynamicSharedMemorySize, SMEMSZ);
    attr_rc = cudaFuncSetAttribute(tgemm_k<0, false, false, false>,
                         cudaFuncAttributeMaxDynamicSharedMemorySize, SMEMSZ);
    attr_rc = cudaFuncSetAttribute(tgemm_k<0, false, true,  false>,
                         cudaFuncAttributeMaxDynamicSharedMemorySize, SMEMSZ);
    attr_rc = cudaFuncSetAttribute(tgemm_k<2, false, false, true>,
                         cudaFuncAttributeMaxDynamicSharedMemorySize, SMEMSZ);
    attr_rc = cudaFuncSetAttribute(tscore_k,
                         cudaFuncAttributeMaxDynamicSharedMemorySize, SMEMSZ);
    (void)attr_rc;

    const long long sHD  = (long long)BS * DD;
    const long long sQKV = (long long)BS * 3 * DD;
    const long long sT   = (long long)BS * 3 * DD;
    dim3 wblk(32, 8);

    // Launch order: ncu profiles OUR launch #4 (router tgemm).
    aconv_k<<<(int)(((long long)BB * NN * DIN + 255) / 256), 256>>>(        // 1
        x, p_x3, DIN, (long long)BB * NN * DIN);
    wconv_k<<<dim3(DD / 32, DIN / 32, 1), wblk>>>(Wr, p_Wr3, DIN, DD);      // 2
    cls_init_k<<<(EE * BB * DD + 255) / 256, 256>>>(cls);                   // 3
    tgemm_k<1, false, false, false><<<dim3(DD / 128, (BB * NN) / 128, 1), 256, SMEMSZ>>>(  // 4
        p_x3, p_Wr3, br, nullptr, p_rbuf, nullptr, BB * NN, DD, 3 * DIN,
        0, 0, 0, 0, 0, 0, 0);
    wconv_k<<<dim3(DD / 32, DIN / 32, EE), wblk>>>(Wp, p_Wp3, DIN, DD);     // 5
    tgemm_k<0, true, false, false><<<dim3(DD / 128, (BB * NN) / 128, EE), 256, SMEMSZ>>>(  // 6
        p_x3, p_Wp3, bp, nullptr, p_h, nullptr, BB * NN, DD, 3 * DIN,
        0, (long long)DD * 3 * DIN, DD, 0, sHD, NN, SS);

    router_reduce_k<<<(BB * DD + 255) / 256, 256>>>();
    gate_k<<<1, 64>>>(Wg, bg, out + BB * DD + BB * NC);

    wconv_k<<<dim3((3 * DD) / 32, DD / 32, EE * LL), wblk>>>(Wqkv, p_Wqkv3, DD, 3 * DD);
    wconv_k<<<dim3(DD / 32, DD / 32, EE * LL), wblk>>>(Wo, p_Wo3, DD, DD);
    wconv_k<<<dim3(MLPD / 32, DD / 32, EE * LL), wblk>>>(Wm1, p_Wm13, DD, MLPD);
    wconv_k<<<dim3(DD / 32, MLPD / 32, EE * LL), wblk>>>(Wm2, p_Wm23, MLPD, DD);

    // --- transformer layers ---
    const int gy = (BS + 127) / 128;   // 33
    for (int l = 0; l < LL; l++) {
        ln3_k<<<dim3(BS, EE), 128>>>(p_h, ln1_g + l * DD, ln1_b + l * DD, p_hn3,
                                     sHD, DD, sT, 3 * DD, (long long)LL * DD);
        tgemm_k<0, false, false, false><<<dim3((3 * DD) / 128, gy, EE), 256, SMEMSZ>>>(
            p_hn3, p_Wqkv3 + (long long)l * (3 * DD) * (3 * DD),
            bqkv + l * 3 * DD, nullptr, p_qkv, nullptr,
            BS, 3 * DD, 3 * DD,
            sT, (long long)LL * (3 * DD) * (3 * DD), (long long)LL * 3 * DD, 0, sQKV, 0, 0);
        // --- tensor attention, sharded per expert ---
        for (int eo = 0; eo < EE; eo++) {
            qk3conv_k<<<dim3(SP, ZB), 64>>>(eo);
            tscore_k<<<dim3(SP / 128, SP / 128, ZB), 256, SMEMSZ>>>();
            softp3_k<<<dim3(SS, ZB), 128>>>();
            vt3conv_k<<<dim3(SP / 64, ZB), 64>>>(eo);
            tav_k<<<dim3(1, SP / 128, ZB), 256>>>(eo);
        }
        // --------------------------------------------
        tgemm_k<0, false, true, false><<<dim3(DD / 128, gy, EE), 256, SMEMSZ>>>(
            p_ao3, p_Wo3 + (long long)l * DD * 3 * DD, bo + l * DD, p_h, p_h, nullptr,
            BS, DD, 3 * DD,
            sT, (long long)LL * DD * 3 * DD, (long long)LL * DD, sHD, sHD, 0, 0);
        ln3_k<<<dim3(BS, EE), 128>>>(p_h, ln2_g + l * DD, ln2_b + l * DD, p_hn3,
                                     sHD, DD, sT, 3 * DD, (long long)LL * DD);
        tgemm_k<2, false, false, true><<<dim3(MLPD / 128, gy, EE), 256, SMEMSZ>>>(
            p_hn3, p_Wm13 + (long long)l * MLPD * 3 * DD, bm1 + l * MLPD,
            nullptr, nullptr, p_mlp3,
            BS, MLPD, 3 * DD,
            sT, (long long)LL * MLPD * 3 * DD, (long long)LL * MLPD, 0,
            (long long)BS * 3 * MLPD, 0, 0);
        tgemm_k<0, false, true, false><<<dim3(DD / 128, gy, EE), 256, SMEMSZ>>>(
            p_mlp3, p_Wm23 + (long long)l * DD * 3 * MLPD, bm2 + l * DD, p_h, p_h, nullptr,
            BS, DD, 3 * MLPD,
            (long long)BS * 3 * MLPD, (long long)LL * DD * 3 * MLPD,
            (long long)LL * DD, sHD, sHD, 0, 0);
    }

    // --- final LN on cls rows -> latents [E,B,D] ---
    ln_k<<<dim3(BB, EE), 128>>>(p_h, lnf_g, lnf_b, p_lat,
                                sHD, (long long)SS * DD,
                                (long long)BB * DD, DD, DD);

    // --- mixture + head ---
    mix_k<<<(BB * DD + 255) / 256, 256>>>(out);
    head_k<<<1, 256>>>(Wh1, bh1, Wh2, bh2, out + BB * DD);
}

// round 17
// speedup vs baseline: 1.2878x; 1.0510x over previous
#include <cuda_runtime.h>
#include <cuda_bf16.h>
#include <cstdint>
#include <math.h>

#define EE   4
#define LL   2
#define BB   4
#define NN   1024
#define SS   1025
#define DIN  2048
#define DD   512
#define HH   8
#define DHD  64
#define MLPD 512
#define NC   4
#define BS   (BB*SS)        // 4100
#define SP   1152           // padded sequence (9*128)
#define SP3  (3*SP)         // 3456
#define KQ   192            // 3*DHD
#define ZB   32             // (b,h) pairs per expert shard

// ---------------- scratch (device globals) ----------------
__device__ float g_h   [(size_t)EE*BS*DD];
__device__ float g_qkv [(size_t)EE*BS*3*DD];
__device__ float g_rbuf[(size_t)BB*NN*DD];
__device__ float g_r   [BB*DD];
__device__ float g_gs  [BB*EE];
__device__ float g_lat [EE*BB*DD];
__device__ float g_mixl[BB*DD];
__device__ __nv_bfloat16 g_x3  [(size_t)BB*NN*3*DIN];
__device__ __nv_bfloat16 g_hn3 [(size_t)EE*BS*3*DD];
__device__ __nv_bfloat16 g_ao3 [(size_t)EE*BS*3*DD];
__device__ __nv_bfloat16 g_mlp3[(size_t)EE*BS*3*MLPD];
__device__ __nv_bfloat16 g_Wr3  [(size_t)DD*3*DIN];
__device__ __nv_bfloat16 g_Wp3  [(size_t)EE*DD*3*DIN];
__device__ __nv_bfloat16 g_Wqkv3[(size_t)EE*LL*(3*DD)*(3*DD)];
__device__ __nv_bfloat16 g_Wo3  [(size_t)EE*LL*DD*(3*DD)];
__device__ __nv_bfloat16 g_Wm13 [(size_t)EE*LL*MLPD*(3*DD)];
__device__ __nv_bfloat16 g_Wm23 [(size_t)EE*LL*DD*(3*MLPD)];
// tensor-attention buffers, per-expert shard of ZB=32 (b,h) pairs
__device__ __nv_bfloat16 g_Q3[(size_t)ZB*SP*KQ];
__device__ __nv_bfloat16 g_K3[(size_t)ZB*SP*KQ];
__device__ float         g_S [(size_t)ZB*SP*SP];
__device__ __nv_bfloat16 g_P3[(size_t)ZB*SP*SP3];
__device__ __nv_bfloat16 g_V3[(size_t)ZB*DHD*SP3];

// ---------------- helpers ----------------
__device__ __forceinline__ uint32_t smem_u32(const void* p) {
    uint32_t a;
    asm("{ .reg .u64 t; cvta.to.shared.u64 t, %1; cvt.u32.u64 %0, t; }" : "=r"(a) : "l"(p));
    return a;
}
#define SW128(off) ((off) ^ (((off) >> 3) & 0x70))

__device__ __forceinline__ void ldm_x4(uint32_t* r, uint32_t addr) {
    asm volatile("ldmatrix.sync.aligned.m8n8.x4.shared.b16 {%0,%1,%2,%3}, [%4];"
        : "=r"(r[0]), "=r"(r[1]), "=r"(r[2]), "=r"(r[3]) : "r"(addr));
}
__device__ __forceinline__ void mma16816(float* d, const uint32_t* a, const uint32_t* b) {
    asm volatile("mma.sync.aligned.m16n8k16.row.col.f32.bf16.bf16.f32 "
        "{%0,%1,%2,%3}, {%4,%5,%6,%7}, {%8,%9}, {%0,%1,%2,%3};"
        : "+f"(d[0]), "+f"(d[1]), "+f"(d[2]), "+f"(d[3])
        : "r"(a[0]), "r"(a[1]), "r"(a[2]), "r"(a[3]), "r"(b[0]), "r"(b[1]));
}
__device__ __forceinline__ void cp16(uint32_t dst, const void* src, int bytes) {
    asm volatile("cp.async.cg.shared.global [%0], [%1], 16, %2;"
        :: "r"(dst), "l"(src), "r"(bytes));
}
#define CP_COMMIT() asm volatile("cp.async.commit_group;" ::: "memory")
#define CP_WAIT1()  asm volatile("cp.async.wait_group 1;" ::: "memory")
#define CP_WAIT0()  asm volatile("cp.async.wait_group 0;" ::: "memory")

__device__ __forceinline__ float gelu_tanh(float x) {
    float x3 = x * x * x;
    float t  = tanhf(0.7978845608028654f * (x + 0.044715f * x3));
    return 0.5f * x * (1.0f + t);
}
__device__ __forceinline__ void split2(float v, __nv_bfloat16& hi, __nv_bfloat16& lo) {
    hi = __float2bfloat16(v);
    lo = __float2bfloat16(v - __bfloat162float(hi));
}
__device__ __forceinline__ float blockReduceSum(float v) {
    __shared__ float sh[32];
    int lane = threadIdx.x & 31, wid = threadIdx.x >> 5;
    #pragma unroll
    for (int o = 16; o > 0; o >>= 1) v += __shfl_xor_sync(0xffffffffu, v, o);
    if (lane == 0) sh[wid] = v;
    __syncthreads();
    int nw = (blockDim.x + 31) >> 5;
    if (wid == 0) {
        float t = (lane < nw) ? sh[lane] : 0.f;
        #pragma unroll
        for (int o = 16; o > 0; o >>= 1) t += __shfl_xor_sync(0xffffffffu, t, o);
        if (lane == 0) sh[0] = t;
    }
    __syncthreads();
    float r = sh[0];
    __syncthreads();
    return r;
}
__device__ __forceinline__ float blockReduceMax(float v) {
    __shared__ float sh[32];
    int lane = threadIdx.x & 31, wid = threadIdx.x >> 5;
    #pragma unroll
    for (int o = 16; o > 0; o >>= 1) v = fmaxf(v, __shfl_xor_sync(0xffffffffu, v, o));
    if (lane == 0) sh[wid] = v;
    __syncthreads();
    int nw = (blockDim.x + 31) >> 5;
    if (wid == 0) {
        float t = (lane < nw) ? sh[lane] : -1e30f;
        #pragma unroll
        for (int o = 16; o > 0; o >>= 1) t = fmaxf(t, __shfl_xor_sync(0xffffffffu, t, o));
        if (lane == 0) sh[0] = t;
    }
    __syncthreads();
    float r = sh[0];
    __syncthreads();
    return r;
}

// =======================================================================
// main tgemm: 128x128 tile, K-chunks of 128 bf16 (two SW128 panels),
// cp.async double-buffer, dynamic smem 128KB
// =======================================================================
template <int ACT, bool REMAP, bool HASRES, bool OUTTRIP>
__global__ __launch_bounds__(256) void tgemm_k(
    const __nv_bfloat16* __restrict__ A3, const __nv_bfloat16* __restrict__ B3,
    const float* __restrict__ bias, const float* __restrict__ Res,
    float* __restrict__ Cf, __nv_bfloat16* __restrict__ Ct,
    int M, int N, int Kp,
    long long sA, long long sB, long long sBias, long long sRes, long long sC,
    int mapN, int mapS)
{
    extern __shared__ __align__(128) char smem[];
    const int tid = threadIdx.x, wid = tid >> 5, lane = tid & 31;
    const long long e = blockIdx.z;
    A3 += e * sA; B3 += e * sB; bias += e * sBias;
    const int brow = blockIdx.y * 128, bcol = blockIdx.x * 128;
    const int wm = wid >> 2, wn = wid & 3;

    float acc[4][4][4];
    #pragma unroll
    for (int i = 0; i < 4; i++)
        #pragma unroll
        for (int j = 0; j < 4; j++)
            #pragma unroll
            for (int f = 0; f < 4; f++) acc[i][j][f] = 0.f;

    const uint32_t sbase = smem_u32(smem);
    const uint32_t sa[2]  = { sbase, sbase + 32768 };
    const uint32_t sbm[2] = { sbase + 65536, sbase + 98304 };

    const int baseRow = tid >> 3;
    const int cb = (tid & 7) * 16;
    uint32_t swoff[4];
    int aok[4]; long long arow[4], browi[4];
    #pragma unroll
    for (int p = 0; p < 4; p++) {
        int row = baseRow + 32 * p;
        swoff[p] = SW128((uint32_t)(row * 128 + cb));
        int gr = brow + row;
        aok[p]  = (gr < M) ? 16 : 0;
        arow[p] = (gr < M) ? gr : (M - 1);
        browi[p] = bcol + row;
    }
    const int NCk = Kp >> 7;    // 128-wide chunks

    // prologue: chunk 0 -> buf 0 (two panels)
    #pragma unroll
    for (int pn = 0; pn < 2; pn++) {
        #pragma unroll
        for (int p = 0; p < 4; p++) {
            cp16(sa[0]  + pn * 16384 + swoff[p],
                 (const char*)(A3 + arow[p]  * Kp + pn * 64) + cb, aok[p]);
            cp16(sbm[0] + pn * 16384 + swoff[p],
                 (const char*)(B3 + browi[p] * Kp + pn * 64) + cb, 16);
        }
    }
    CP_COMMIT();

    for (int c = 0; c < NCk; c++) {
        const int buf = c & 1;
        if (c + 1 < NCk) {
            const int nb = buf ^ 1;
            #pragma unroll
            for (int pn = 0; pn < 2; pn++) {
                #pragma unroll
                for (int p = 0; p < 4; p++) {
                    cp16(sa[nb]  + pn * 16384 + swoff[p],
                         (const char*)(A3 + arow[p]  * Kp + (c + 1) * 128 + pn * 64) + cb, aok[p]);
                    cp16(sbm[nb] + pn * 16384 + swoff[p],
                         (const char*)(B3 + browi[p] * Kp + (c + 1) * 128 + pn * 64) + cb, 16);
                }
            }
            CP_COMMIT();
            CP_WAIT1();
        } else {
            CP_WAIT0();
        }
        __syncthreads();

        #pragma unroll
        for (int pn = 0; pn < 2; pn++) {
            const uint32_t asb = sa[buf] + pn * 16384, bsb = sbm[buf] + pn * 16384;
            #pragma unroll
            for (int ks = 0; ks < 4; ks++) {
                uint32_t afr[4][4], bfr[2][4];
                #pragma unroll
                for (int mi = 0; mi < 4; mi++) {
                    int ar = wm * 64 + mi * 16 + (lane & 15);
                    int ac = ks * 32 + (lane >> 4) * 16;
                    ldm_x4(afr[mi], asb + SW128((uint32_t)(ar * 128 + ac)));
                }
                #pragma unroll
                for (int np = 0; np < 2; np++) {
                    int nr = wn * 32 + np * 16 + (lane & 7) + ((lane >> 4) & 1) * 8;
                    int bc = ks * 32 + ((lane >> 3) & 1) * 16;
                    ldm_x4(bfr[np], bsb + SW128((uint32_t)(nr * 128 + bc)));
                }
                #pragma unroll
                for (int mi = 0; mi < 4; mi++)
                    #pragma unroll
                    for (int ni = 0; ni < 4; ni++)
                        mma16816(acc[mi][ni], afr[mi], &bfr[ni >> 1][(ni & 1) * 2]);
            }
        }
        __syncthreads();
    }

    #pragma unroll
    for (int mi = 0; mi < 4; mi++) {
        #pragma unroll
        for (int half = 0; half < 2; half++) {
            int row = brow + wm * 64 + mi * 16 + (lane >> 2) + half * 8;
            if (row >= M) continue;
            long long orow = row;
            if (REMAP) orow = (long long)(row / mapN) * mapS + 1 + (row % mapN);
            #pragma unroll
            for (int ni = 0; ni < 4; ni++) {
                int col = bcol + wn * 32 + ni * 8 + (lane & 3) * 2;
                float v0 = acc[mi][ni][half * 2 + 0] + bias[col];
                float v1 = acc[mi][ni][half * 2 + 1] + bias[col + 1];
                if (HASRES) {
                    float2 rr = *(const float2*)(Res + e * sRes + orow * (long long)N + col);
                    v0 += rr.x; v1 += rr.y;
                }
                if (ACT == 1) { v0 = fmaxf(v0, 0.f); v1 = fmaxf(v1, 0.f); }
                else if (ACT == 2) { v0 = gelu_tanh(v0); v1 = gelu_tanh(v1); }
                if (OUTTRIP) {
                    __nv_bfloat16* op = Ct + e * sC + orow * (long long)(3 * N) + 3 * col;
                    __nv_bfloat16 h0, l0, h1, l1;
                    split2(v0, h0, l0); split2(v1, h1, l1);
                    op[0] = h0; op[1] = h0; op[2] = l0;
                    op[3] = h1; op[4] = h1; op[5] = l1;
                } else {
                    float* cp = Cf + e * sC + orow * (long long)N + col;
                    *(float2*)cp = make_float2(v0, v1);
                }
            }
        }
    }
}

// =======================================================================
// tscore_k: S[zl][q][k] = 0.125 * Q3[zl] . K3[zl]^T ; K=192 (3x64 chunks)
// grid (9,9,ZB); dynamic smem 64KB
// =======================================================================
__global__ __launch_bounds__(256) void tscore_k()
{
    extern __shared__ __align__(128) char smem[];
    const int tid = threadIdx.x, wid = tid >> 5, lane = tid & 31;
    const long long z = blockIdx.z;
    const __nv_bfloat16* A3 = g_Q3 + z * (long long)SP * KQ;
    const __nv_bfloat16* B3 = g_K3 + z * (long long)SP * KQ;
    float* Cf = g_S + z * (long long)SP * SP;
    const int brow = blockIdx.y * 128, bcol = blockIdx.x * 128;
    const int wm = wid >> 2, wn = wid & 3;

    float acc[4][4][4];
    #pragma unroll
    for (int i = 0; i < 4; i++)
        #pragma unroll
        for (int j = 0; j < 4; j++)
            #pragma unroll
            for (int f = 0; f < 4; f++) acc[i][j][f] = 0.f;

    const uint32_t sbase = smem_u32(smem);
    const uint32_t sa[2]  = { sbase, sbase + 16384 };
    const uint32_t sbm[2] = { sbase + 32768, sbase + 49152 };

    const int baseRow = tid >> 3;
    const int cb = (tid & 7) * 16;
    uint32_t swoff[4];
    long long arow[4], browi[4];
    #pragma unroll
    for (int p = 0; p < 4; p++) {
        int row = baseRow + 32 * p;
        swoff[p] = SW128((uint32_t)(row * 128 + cb));
        arow[p]  = brow + row;
        browi[p] = bcol + row;
    }

    #pragma unroll
    for (int p = 0; p < 4; p++) {
        cp16(sa[0]  + swoff[p], (const char*)(A3 + arow[p]  * KQ) + cb, 16);
        cp16(sbm[0] + swoff[p], (const char*)(B3 + browi[p] * KQ) + cb, 16);
    }
    CP_COMMIT();

    for (int c = 0; c < 3; c++) {
        const int buf = c & 1;
        if (c + 1 < 3) {
            const int nb = buf ^ 1;
            #pragma unroll
            for (int p = 0; p < 4; p++) {
                cp16(sa[nb]  + swoff[p],
                     (const char*)(A3 + arow[p]  * KQ + (c + 1) * 64) + cb, 16);
                cp16(sbm[nb] + swoff[p],
                     (const char*)(B3 + browi[p] * KQ + (c + 1) * 64) + cb, 16);
            }
            CP_COMMIT();
            CP_WAIT1();
        } else {
            CP_WAIT0();
        }
        __syncthreads();

        const uint32_t asb = sa[buf], bsb = sbm[buf];
        #pragma unroll
        for (int ks = 0; ks < 4; ks++) {
            uint32_t afr[4][4], bfr[2][4];
            #pragma unroll
            for (int mi = 0; mi < 4; mi++) {
                int ar = wm * 64 + mi * 16 + (lane & 15);
                int ac = ks * 32 + (lane >> 4) * 16;
                ldm_x4(afr[mi], asb + SW128((uint32_t)(ar * 128 + ac)));
            }
            #pragma unroll
            for (int np = 0; np < 2; np++) {
                int nr = wn * 32 + np * 16 + (lane & 7) + ((lane >> 4) & 1) * 8;
                int bc = ks * 32 + ((lane >> 3) & 1) * 16;
                ldm_x4(bfr[np], bsb + SW128((uint32_t)(nr * 128 + bc)));
            }
            #pragma unroll
            for (int mi = 0; mi < 4; mi++)
                #pragma unroll
                for (int ni = 0; ni < 4; ni++)
                    mma16816(acc[mi][ni], afr[mi], &bfr[ni >> 1][(ni & 1) * 2]);
        }
        __syncthreads();
    }

    #pragma unroll
    for (int mi = 0; mi < 4; mi++) {
        #pragma unroll
        for (int half = 0; half < 2; half++) {
            int row = brow + wm * 64 + mi * 16 + (lane >> 2) + half * 8;
            #pragma unroll
            for (int ni = 0; ni < 4; ni++) {
                int col = bcol + wn * 32 + ni * 8 + (lane & 3) * 2;
                float v0 = acc[mi][ni][half * 2 + 0] * 0.125f;
                float v1 = acc[mi][ni][half * 2 + 1] * 0.125f;
                *(float2*)(Cf + (long long)row * SP + col) = make_float2(v0, v1);
            }
        }
    }
}

// =======================================================================
// tav_k: O[zl] = P3[zl] . V3[zl]^T ; 128x64 tile, K-chunks of 128 (2 panels)
// dynamic smem 96KB; grid (1, 9, ZB); triplet epilogue into g_ao3
// =======================================================================
__global__ __launch_bounds__(256) void tav_k(int eo)
{
    extern __shared__ __align__(128) char smem[];
    const int tid = threadIdx.x, wid = tid >> 5, lane = tid & 31;
    const int zl = blockIdx.z;
    const int b = (zl >> 3) & 3, h = zl & 7;
    const __nv_bfloat16* A3 = g_P3 + (long long)zl * SP * SP3;
    const __nv_bfloat16* B3 = g_V3 + (long long)zl * DHD * SP3;
    const int brow = blockIdx.y * 128;
    const int wm = wid >> 1, wn = wid & 1;

    float acc[2][4][4];
    #pragma unroll
    for (int i = 0; i < 2; i++)
        #pragma unroll
        for (int j = 0; j < 4; j++)
            #pragma unroll
            for (int f = 0; f < 4; f++) acc[i][j][f] = 0.f;

    const uint32_t sbase = smem_u32(smem);
    const uint32_t sa[2]  = { sbase, sbase + 32768 };            // 2 x 32KB (A)
    const uint32_t sbm[2] = { sbase + 65536, sbase + 81920 };    // 2 x 16KB (B)

    const int baseRow = tid >> 3;
    const int cb = (tid & 7) * 16;
    uint32_t swoff[4];
    int aok[4]; long long arow[4];
    #pragma unroll
    for (int p = 0; p < 4; p++) {
        int row = baseRow + 32 * p;
        swoff[p] = SW128((uint32_t)(row * 128 + cb));
        int gr = brow + row;
        aok[p]  = (gr < SS) ? 16 : 0;
        arow[p] = (gr < SS) ? gr : (SS - 1);
    }
    long long browi[2] = { baseRow, baseRow + 32 };
    const int NCk = SP3 >> 7;    // 27 chunks of 128

    #pragma unroll
    for (int pn = 0; pn < 2; pn++) {
        #pragma unroll
        for (int p = 0; p < 4; p++)
            cp16(sa[0] + pn * 16384 + swoff[p],
                 (const char*)(A3 + arow[p] * SP3 + pn * 64) + cb, aok[p]);
        #pragma unroll
        for (int p = 0; p < 2; p++)
            cp16(sbm[0] + pn * 8192 + swoff[p],
                 (const char*)(B3 + browi[p] * SP3 + pn * 64) + cb, 16);
    }
    CP_COMMIT();

    for (int c = 0; c < NCk; c++) {
        const int buf = c & 1;
        if (c + 1 < NCk) {
            const int nb = buf ^ 1;
            #pragma unroll
            for (int pn = 0; pn < 2; pn++) {
                #pragma unroll
                for (int p = 0; p < 4; p++)
                    cp16(sa[nb] + pn * 16384 + swoff[p],
                         (const char*)(A3 + arow[p] * SP3 + (c + 1) * 128 + pn * 64) + cb, aok[p]);
                #pragma unroll
                for (int p = 0; p < 2; p++)
                    cp16(sbm[nb] + pn * 8192 + swoff[p],
                         (const char*)(B3 + browi[p] * SP3 + (c + 1) * 128 + pn * 64) + cb, 16);
            }
            CP_COMMIT();
            CP_WAIT1();
        } else {
            CP_WAIT0();
        }
        __syncthreads();

        #pragma unroll
        for (int pn = 0; pn < 2; pn++) {
            const uint32_t asb = sa[buf] + pn * 16384, bsb = sbm[buf] + pn * 8192;
            #pragma unroll
            for (int ks = 0; ks < 4; ks++) {
                uint32_t afr[2][4], bfr[2][4];
                #pragma unroll
                for (int mi = 0; mi < 2; mi++) {
                    int ar = wm * 32 + mi * 16 + (lane & 15);
                    int ac = ks * 32 + (lane >> 4) * 16;
                    ldm_x4(afr[mi], asb + SW128((uint32_t)(ar * 128 + ac)));
                }
                #pragma unroll
                for (int np = 0; np < 2; np++) {
                    int nr = wn * 32 + np * 16 + (lane & 7) + ((lane >> 4) & 1) * 8;
                    int bc = ks * 32 + ((lane >> 3) & 1) * 16;
                    ldm_x4(bfr[np], bsb + SW128((uint32_t)(nr * 128 + bc)));
                }
                #pragma unroll
                for (int mi = 0; mi < 2; mi++)
                    #pragma unroll
                    for (int ni = 0; ni < 4; ni++)
                        mma16816(acc[mi][ni], afr[mi], &bfr[ni >> 1][(ni & 1) * 2]);
            }
        }
        __syncthreads();
    }

    #pragma unroll
    for (int mi = 0; mi < 2; mi++) {
        #pragma unroll
        for (int half = 0; half < 2; half++) {
            int row = brow + wm * 32 + mi * 16 + (lane >> 2) + half * 8;
            if (row >= SS) continue;
            __nv_bfloat16* op = g_ao3 +
                ((long long)(eo * BS + b * SS) + row) * (3 * DD) + 3 * (h * DHD);
            #pragma unroll
            for (int ni = 0; ni < 4; ni++) {
                int col = wn * 32 + ni * 8 + (lane & 3) * 2;
                float v0 = acc[mi][ni][half * 2 + 0];
                float v1 = acc[mi][ni][half * 2 + 1];
                __nv_bfloat16 h0, l0, h1, l1;
                split2(v0, h0, l0); split2(v1, h1, l1);
                op[3 * col]     = h0; op[3 * col + 1] = h0; op[3 * col + 2] = l0;
                op[3 * col + 3] = h1; op[3 * col + 4] = h1; op[3 * col + 5] = l1;
            }
        }
    }
}

// ---------------- attention conversions (per-expert shard) ----------------
__global__ void qk3conv_k(int eo) {
    const int row = blockIdx.x, zl = blockIdx.y, d = threadIdx.x;
    const int b = (zl >> 3) & 3, h = zl & 7;
    float qv = 0.f, kv = 0.f;
    if (row < SS) {
        const float* p = g_qkv + (((long long)eo * BS + b * SS + row) * 3 * DD) + h * DHD + d;
        qv = p[0]; kv = p[DD];
    }
    __nv_bfloat16 qh, ql, kh, kl;
    split2(qv, qh, ql); split2(kv, kh, kl);
    long long base = ((long long)zl * SP + row) * KQ + 3 * d;
    g_Q3[base] = qh; g_Q3[base + 1] = qh; g_Q3[base + 2] = ql;
    g_K3[base] = kh; g_K3[base + 1] = kl; g_K3[base + 2] = kh;
}

__global__ void vt3conv_k(int eo) {
    __shared__ float sm[64][65];
    const int k0 = blockIdx.x * 64, zl = blockIdx.y, t = threadIdx.x;
    const int b = (zl >> 3) & 3, h = zl & 7;
    for (int i = 0; i < 64; i++) {
        int k = k0 + i;
        sm[t][i] = (k < SS)
            ? g_qkv[(((long long)eo * BS + b * SS + k) * 3 * DD) + 2 * DD + h * DHD + t]
            : 0.f;
    }
    __syncthreads();
    __nv_bfloat16* op = g_V3 + ((long long)zl * DHD + t) * SP3 + 3 * k0;
    for (int i = 0; i < 64; i++) {
        __nv_bfloat16 hi, lo; split2(sm[t][i], hi, lo);
        op[3 * i] = hi; op[3 * i + 1] = lo; op[3 * i + 2] = hi;
    }
}

__global__ __launch_bounds__(128) void softp3_k() {
    __shared__ float se[1028];
    const int q = blockIdx.x, zl = blockIdx.y, tid = threadIdx.x;
    const float* s = g_S + ((long long)zl * SP + q) * SP;
    float mx = -1e30f;
    for (int k = tid; k < SS; k += 128) mx = fmaxf(mx, s[k]);
    mx = blockReduceMax(mx);
    float sum = 0.f;
    for (int k = tid; k < SS; k += 128) {
        float ev = __expf(s[k] - mx);
        se[k] = ev;
        sum += ev;
    }
    sum = blockReduceSum(sum);
    const float inv = 1.f / sum;
    __nv_bfloat16* p = g_P3 + ((long long)zl * SP + q) * SP3;
    __syncthreads();
    for (int k = tid; k < SS; k += 128) {
        __nv_bfloat16 hi, lo; split2(se[k] * inv, hi, lo);
        p[3 * k] = hi; p[3 * k + 1] = hi; p[3 * k + 2] = lo;
    }
    const __nv_bfloat16 zz = __float2bfloat16(0.f);
    for (int k = SS + tid; k < SP; k += 128) {
        p[3 * k] = zz; p[3 * k + 1] = zz; p[3 * k + 2] = zz;
    }
}

// ---------------- existing conversions ----------------
__global__ void aconv_k(const float* __restrict__ X, __nv_bfloat16* __restrict__ X3,
                        int Kdim, long long total)
{
    long long idx = (long long)blockIdx.x * blockDim.x + threadIdx.x;
    if (idx >= total) return;
    long long m = idx / Kdim;
    int k = (int)(idx - m * Kdim);
    __nv_bfloat16 hi, lo; split2(X[idx], hi, lo);
    long long base = m * (long long)(3 * Kdim) + 3 * k;
    X3[base] = hi; X3[base + 1] = hi; X3[base + 2] = lo;
}

__global__ void wconv_k(const float* __restrict__ W, __nv_bfloat16* __restrict__ W3,
                        int K, int N)
{
    __shared__ float t[32][33];
    const int n0 = blockIdx.x * 32, k0 = blockIdx.y * 32;
    const float* Wb = W + (long long)blockIdx.z * K * N;
    __nv_bfloat16* Ob = W3 + (long long)blockIdx.z * N * 3 * K;
    const int tx = threadIdx.x, ty = threadIdx.y;
    for (int i = ty; i < 32; i += 8)
        t[i][tx] = Wb[(long long)(k0 + i) * N + n0 + tx];
    __syncthreads();
    for (int i = ty; i < 32; i += 8) {
        int n = n0 + i;
        __nv_bfloat16 hi, lo; split2(t[tx][i], hi, lo);
        long long base = (long long)n * 3 * K + 3 * (k0 + tx);
        Ob[base] = hi; Ob[base + 1] = lo; Ob[base + 2] = hi;
    }
}

// ---------------- LayerNorms ----------------
__global__ __launch_bounds__(128) void ln3_k(
    const float* __restrict__ X, const float* __restrict__ G,
    const float* __restrict__ Bt, __nv_bfloat16* __restrict__ Y3,
    long long xb, long long xr, long long yb, long long yr, long long gs)
{
    const long long e = blockIdx.y;
    const float* x = X + e * xb + (long long)blockIdx.x * xr;
    __nv_bfloat16* y = Y3 + e * yb + (long long)blockIdx.x * yr;
    const float* g = G + e * gs;
    const float* b = Bt + e * gs;
    const int tid = threadIdx.x;

    float4 v = *(const float4*)(x + tid * 4);
    float s = blockReduceSum(v.x + v.y + v.z + v.w);
    float mean = s * (1.f / 512.f);
    float dx = v.x - mean, dy = v.y - mean, dz = v.z - mean, dw = v.w - mean;
    float s2 = blockReduceSum(dx * dx + dy * dy + dz * dz + dw * dw);
    float rstd = rsqrtf(s2 * (1.f / 512.f) + 1e-5f);
    float4 gv = *(const float4*)(g + tid * 4);
    float4 bv = *(const float4*)(b + tid * 4);
    float o[4] = { dx * rstd * gv.x + bv.x, dy * rstd * gv.y + bv.y,
                   dz * rstd * gv.z + bv.z, dw * rstd * gv.w + bv.w };
    #pragma unroll
    for (int j = 0; j < 4; j++) {
        __nv_bfloat16 hi, lo; split2(o[j], hi, lo);
        long long base = 3 * (long long)(tid * 4 + j);
        y[base] = hi; y[base + 1] = hi; y[base + 2] = lo;
    }
}

__global__ __launch_bounds__(128) void ln_k(
    const float* __restrict__ X, const float* __restrict__ G,
    const float* __restrict__ Bt, float* __restrict__ Y,
    long long xb, long long xr, long long yb, long long yr, long long gs)
{
    const long long e = blockIdx.y;
    const float* x = X + e * xb + (long long)blockIdx.x * xr;
    float*       y = Y + e * yb + (long long)blockIdx.x * yr;
    const float* g = G + e * gs;
    const float* b = Bt + e * gs;
    const int tid = threadIdx.x;

    float4 v = *(const float4*)(x + tid * 4);
    float s = blockReduceSum(v.x + v.y + v.z + v.w);
    float mean = s * (1.f / 512.f);
    float dx = v.x - mean, dy = v.y - mean, dz = v.z - mean, dw = v.w - mean;
    float s2 = blockReduceSum(dx * dx + dy * dy + dz * dz + dw * dw);
    float rstd = rsqrtf(s2 * (1.f / 512.f) + 1e-5f);
    float4 gv = *(const float4*)(g + tid * 4);
    float4 bv = *(const float4*)(b + tid * 4);
    float4 o;
    o.x = dx * rstd * gv.x + bv.x;
    o.y = dy * rstd * gv.y + bv.y;
    o.z = dz * rstd * gv.z + bv.z;
    o.w = dw * rstd * gv.w + bv.w;
    *(float4*)(y + tid * 4) = o;
}

__global__ void cls_init_k(const float* __restrict__ cls) {
    int idx = blockIdx.x * blockDim.x + threadIdx.x;
    if (idx >= EE * BB * DD) return;
    int d = idx & (DD - 1);
    int r = idx >> 9;
    int b = r & (BB - 1);
    int e = r >> 2;
    g_h[((long long)e * BS + (long long)b * SS) * DD + d] = cls[e * DD + d];
}

// ---------------- router / gate / mix / head ----------------
__global__ void router_reduce_k() {
    int idx = blockIdx.x * blockDim.x + threadIdx.x;
    if (idx >= BB * DD) return;
    int b = idx >> 9, d = idx & (DD - 1);
    const float* p = g_rbuf + (long long)b * NN * DD + d;
    float s = 0.f;
    for (int n = 0; n < NN; n++) s += p[(long long)n * DD];
    g_r[idx] = s * (1.f / (float)NN);
}

__global__ void gate_k(const float* __restrict__ Wg, const float* __restrict__ bg,
                       float* __restrict__ out_g) {
    __shared__ float lg[BB][EE];
    int tid = threadIdx.x;
    if (tid < BB * EE) {
        int b = tid >> 2, e = tid & 3;
        float s = bg[e];
        for (int k = 0; k < DD; k++) s = fmaf(g_r[b * DD + k], Wg[k * EE + e], s);
        lg[b][e] = s;
    }
    __syncthreads();
    if (tid < BB) {
        int b = tid;
        float mx = fmaxf(fmaxf(lg[b][0], lg[b][1]), fmaxf(lg[b][2], lg[b][3]));
        float ex[EE], s = 0.f;
        #pragma unroll
        for (int e = 0; e < EE; e++) { ex[e] = expf(lg[b][e] - mx); s += ex[e]; }
        #pragma unroll
        for (int e = 0; e < EE; e++) {
            float g = ex[e] / s;
            g_gs[b * EE + e] = g;
            out_g[b * EE + e] = g;
        }
    }
}

__global__ void mix_k(float* __restrict__ out_latent) {
    int idx = blockIdx.x * blockDim.x + threadIdx.x;
    if (idx >= BB * DD) return;
    int b = idx >> 9, d = idx & (DD - 1);
    float s = 0.f;
    #pragma unroll
    for (int e = 0; e < EE; e++)
        s = fmaf(g_gs[b * EE + e], g_lat[(e * BB + b) * DD + d], s);
    g_mixl[idx] = s;
    out_latent[idx] = s;
}

__global__ void head_k(const float* __restrict__ Wh1, const float* __restrict__ bh1,
                       const float* __restrict__ Wh2, const float* __restrict__ bh2,
                       float* __restrict__ out_logits) {
    __shared__ float hid[BB][64];
    int tid = threadIdx.x;
    {
        int b = tid >> 6, j = tid & 63;
        float s = bh1[j];
        for (int k = 0; k < DD; k++) s = fmaf(g_mixl[b * DD + k], Wh1[k * 64 + j], s);
        hid[b][j] = fmaxf(s, 0.f);
    }
    __syncthreads();
    if (tid < BB * NC) {
        int b = tid >> 2, c = tid & 3;
        float s = bh2[c];
        #pragma unroll
        for (int k = 0; k < 64; k++) s = fmaf(hid[b][k], Wh2[k * NC + c], s);
        out_logits[b * NC + c] = s;
    }
}

// =======================================================================
extern "C" void kernel_launch(void* const* d_in, const int* in_sizes, int n_in,
                              void* d_out, int out_size)
{
    const float* x     = (const float*)d_in[0];
    const float* Wp    = (const float*)d_in[1];
    const float* bp    = (const float*)d_in[2];
    const float* cls   = (const float*)d_in[3];
    const float* ln1_g = (const float*)d_in[4];
    const float* ln1_b = (const float*)d_in[5];
    const float* Wqkv  = (const float*)d_in[6];
    const float* bqkv  = (const float*)d_in[7];
    const float* Wo    = (const float*)d_in[8];
    const float* bo    = (const float*)d_in[9];
    const float* ln2_g = (const float*)d_in[10];
    const float* ln2_b = (const float*)d_in[11];
    const float* Wm1   = (const float*)d_in[12];
    const float* bm1   = (const float*)d_in[13];
    const float* Wm2   = (const float*)d_in[14];
    const float* bm2   = (const float*)d_in[15];
    const float* lnf_g = (const float*)d_in[16];
    const float* lnf_b = (const float*)d_in[17];
    const float* Wr    = (const float*)d_in[18];
    const float* br    = (const float*)d_in[19];
    const float* Wg    = (const float*)d_in[20];
    const float* bg    = (const float*)d_in[21];
    const float* Wh1   = (const float*)d_in[22];
    const float* bh1   = (const float*)d_in[23];
    const float* Wh2   = (const float*)d_in[24];
    const float* bh2   = (const float*)d_in[25];
    float* out = (float*)d_out;

    float *p_h, *p_qkv, *p_rbuf, *p_lat;
    __nv_bfloat16 *p_x3, *p_hn3, *p_ao3, *p_mlp3;
    __nv_bfloat16 *p_Wr3, *p_Wp3, *p_Wqkv3, *p_Wo3, *p_Wm13, *p_Wm23;
    cudaGetSymbolAddress((void**)&p_h,     g_h);
    cudaGetSymbolAddress((void**)&p_qkv,   g_qkv);
    cudaGetSymbolAddress((void**)&p_rbuf,  g_rbuf);
    cudaGetSymbolAddress((void**)&p_lat,   g_lat);
    cudaGetSymbolAddress((void**)&p_x3,    g_x3);
    cudaGetSymbolAddress((void**)&p_hn3,   g_hn3);
    cudaGetSymbolAddress((void**)&p_ao3,   g_ao3);
    cudaGetSymbolAddress((void**)&p_mlp3,  g_mlp3);
    cudaGetSymbolAddress((void**)&p_Wr3,   g_Wr3);
    cudaGetSymbolAddress((void**)&p_Wp3,   g_Wp3);
    cudaGetSymbolAddress((void**)&p_Wqkv3, g_Wqkv3);
    cudaGetSymbolAddress((void**)&p_Wo3,   g_Wo3);
    cudaGetSymbolAddress((void**)&p_Wm13,  g_Wm13);
    cudaGetSymbolAddress((void**)&p_Wm23,  g_Wm23);

    const int SMEMG = 131072;   // tgemm: 128KB
    const int SMEMS = 65536;    // tscore: 64KB
    const int SMEMV = 98304;    // tav: 96KB
    cudaError_t attr_rc = cudaSuccess;
    attr_rc = cudaFuncSetAttribute(tgemm_k<1, false, false, false>,
                         cudaFuncAttributeMaxDynamicSharedMemorySize, SMEMG);
    attr_rc = cudaFuncSetAttribute(tgemm_k<0, true,  false, false>,
                         cudaFuncAttributeMaxDynamicSharedMemorySize, SMEMG);
    attr_rc = cudaFuncSetAttribute(tgemm_k<0, false, false, false>,
                         cudaFuncAttributeMaxDynamicSharedMemorySize, SMEMG);
    attr_rc = cudaFuncSetAttribute(tgemm_k<0, false, true,  false>,
                         cudaFuncAttributeMaxDynamicSharedMemorySize, SMEMG);
    attr_rc = cudaFuncSetAttribute(tgemm_k<2, false, false, true>,
                         cudaFuncAttributeMaxDynamicSharedMemorySize, SMEMG);
    attr_rc = cudaFuncSetAttribute(tscore_k,
                         cudaFuncAttributeMaxDynamicSharedMemorySize, SMEMS);
    attr_rc = cudaFuncSetAttribute(tav_k,
                         cudaFuncAttributeMaxDynamicSharedMemorySize, SMEMV);
    (void)attr_rc;

    const long long sHD  = (long long)BS * DD;
    const long long sQKV = (long long)BS * 3 * DD;
    const long long sT   = (long long)BS * 3 * DD;
    dim3 wblk(32, 8);

    // Launch order: ncu profiles OUR launch #4 (router tgemm).
    aconv_k<<<(int)(((long long)BB * NN * DIN + 255) / 256), 256>>>(        // 1
        x, p_x3, DIN, (long long)BB * NN * DIN);
    wconv_k<<<dim3(DD / 32, DIN / 32, 1), wblk>>>(Wr, p_Wr3, DIN, DD);      // 2
    cls_init_k<<<(EE * BB * DD + 255) / 256, 256>>>(cls);                   // 3
    tgemm_k<1, false, false, false><<<dim3(DD / 128, (BB * NN) / 128, 1), 256, SMEMG>>>(  // 4
        p_x3, p_Wr3, br, nullptr, p_rbuf, nullptr, BB * NN, DD, 3 * DIN,
        0, 0, 0, 0, 0, 0, 0);
    wconv_k<<<dim3(DD / 32, DIN / 32, EE), wblk>>>(Wp, p_Wp3, DIN, DD);     // 5
    tgemm_k<0, true, false, false><<<dim3(DD / 128, (BB * NN) / 128, EE), 256, SMEMG>>>(  // 6
        p_x3, p_Wp3, bp, nullptr, p_h, nullptr, BB * NN, DD, 3 * DIN,
        0, (long long)DD * 3 * DIN, DD, 0, sHD, NN, SS);

    router_reduce_k<<<(BB * DD + 255) / 256, 256>>>();
    gate_k<<<1, 64>>>(Wg, bg, out + BB * DD + BB * NC);

    wconv_k<<<dim3((3 * DD) / 32, DD / 32, EE * LL), wblk>>>(Wqkv, p_Wqkv3, DD, 3 * DD);
    wconv_k<<<dim3(DD / 32, DD / 32, EE * LL), wblk>>>(Wo, p_Wo3, DD, DD);
    wconv_k<<<dim3(MLPD / 32, DD / 32, EE * LL), wblk>>>(Wm1, p_Wm13, DD, MLPD);
    wconv_k<<<dim3(DD / 32, MLPD / 32, EE * LL), wblk>>>(Wm2, p_Wm23, MLPD, DD);

    // --- transformer layers ---
    const int gy = (BS + 127) / 128;   // 33
    for (int l = 0; l < LL; l++) {
        ln3_k<<<dim3(BS, EE), 128>>>(p_h, ln1_g + l * DD, ln1_b + l * DD, p_hn3,
                                     sHD, DD, sT, 3 * DD, (long long)LL * DD);
        tgemm_k<0, false, false, false><<<dim3((3 * DD) / 128, gy, EE), 256, SMEMG>>>(
            p_hn3, p_Wqkv3 + (long long)l * (3 * DD) * (3 * DD),
            bqkv + l * 3 * DD, nullptr, p_qkv, nullptr,
            BS, 3 * DD, 3 * DD,
            sT, (long long)LL * (3 * DD) * (3 * DD), (long long)LL * 3 * DD, 0, sQKV, 0, 0);
        // --- tensor attention, sharded per expert ---
        for (int eo = 0; eo < EE; eo++) {
            qk3conv_k<<<dim3(SP, ZB), 64>>>(eo);
            tscore_k<<<dim3(SP / 128, SP / 128, ZB), 256, SMEMS>>>();
            softp3_k<<<dim3(SS, ZB), 128>>>();
            vt3conv_k<<<dim3(SP / 64, ZB), 64>>>(eo);
            tav_k<<<dim3(1, SP / 128, ZB), 256, SMEMV>>>(eo);
        }
        // --------------------------------------------
        tgemm_k<0, false, true, false><<<dim3(DD / 128, gy, EE), 256, SMEMG>>>(
            p_ao3, p_Wo3 + (long long)l * DD * 3 * DD, bo + l * DD, p_h, p_h, nullptr,
            BS, DD, 3 * DD,
            sT, (long long)LL * DD * 3 * DD, (long long)LL * DD, sHD, sHD, 0, 0);
        ln3_k<<<dim3(BS, EE), 128>>>(p_h, ln2_g + l * DD, ln2_b + l * DD, p_hn3,
                                     sHD, DD, sT, 3 * DD, (long long)LL * DD);
        tgemm_k<2, false, false, true><<<dim3(MLPD / 128, gy, EE), 256, SMEMG>>>(
            p_hn3, p_Wm13 + (long long)l * MLPD * 3 * DD, bm1 + l * MLPD,
            nullptr, nullptr, p_mlp3,
            BS, MLPD, 3 * DD,
            sT, (long long)LL * MLPD * 3 * DD, (long long)LL * MLPD, 0,
            (long long)BS * 3 * MLPD, 0, 0);
        tgemm_k<0, false, true, false><<<dim3(DD / 128, gy, EE), 256, SMEMG>>>(
            p_mlp3, p_Wm23 + (long long)l * DD * 3 * MLPD, bm2 + l * DD, p_h, p_h, nullptr,
            BS, DD, 3 * MLPD,
            (long long)BS * 3 * MLPD, (long long)LL * DD * 3 * MLPD,
            (long long)LL * DD, sHD, sHD, 0, 0);
    }

    // --- final LN on cls rows -> latents [E,B,D] ---
    ln_k<<<dim3(BB, EE), 128>>>(p_h, lnf_g, lnf_b, p_lat,
                                sHD, (long long)SS * DD,
                                (long long)BB * DD, DD, DD);

    // --- mixture + head ---
    mix_k<<<(BB * DD + 255) / 256, 256>>>(out);
    head_k<<<1, 256>>>(Wh1, bh1, Wh2, bh2, out + BB * DD);
}